// round 1
// baseline (speedup 1.0000x reference)
#include <cuda_runtime.h>
#include <math.h>

#define Bdim 4
#define Sdim 2048
#define Ddim 1024
#define Hdim 16
#define DKdim 64
#define Mtot (Bdim*Sdim)   // 8192

// Scratch (device globals are the sanctioned no-alloc workaround)
__device__ float g_Q[Bdim*Hdim*Sdim*DKdim];   // [b,h,s,dk]
__device__ float g_K[Bdim*Hdim*Sdim*DKdim];
__device__ float g_V[Bdim*Hdim*Sdim*DKdim];
__device__ float g_ctx[Bdim*Sdim*Ddim];       // [b,s,d]

// ---------------------------------------------------------------------------
// SGEMM-NT: C[m,n] = sum_k A[m,k]*W[n,k] + bias[n]
// A: [M,K] row-major, W: [N,K] row-major. BM=BN=128, BK=16, 256 thr, 8x8/thr.
// SCATTER=true writes to [b,h,s,dk] (QKV projections); else [m,n] linear.
// ---------------------------------------------------------------------------
template<bool SCATTER>
__global__ void __launch_bounds__(256, 2)
gemm_kernel(const float* __restrict__ A, const float* __restrict__ W,
            const float* __restrict__ bias, float* __restrict__ Cout, int Kdim)
{
    __shared__ float As[16][132];   // stored transposed: As[k][m]
    __shared__ float Bs[16][132];   // Bs[k][n]

    const int tid = threadIdx.x;
    const int tx = tid & 15, ty = tid >> 4;
    const int m0 = blockIdx.y * 128;
    const int n0 = blockIdx.x * 128;

    float acc[8][8];
#pragma unroll
    for (int i = 0; i < 8; i++)
#pragma unroll
        for (int j = 0; j < 8; j++) acc[i][j] = 0.f;

    const int lrow = tid >> 2;        // 0..63
    const int lc4  = (tid & 3) << 2;  // 0,4,8,12

    for (int k0 = 0; k0 < Kdim; k0 += 16) {
#pragma unroll
        for (int t = 0; t < 2; t++) {
            const int row = lrow + t * 64;
            float4 av = *(const float4*)(A + (size_t)(m0 + row) * Kdim + k0 + lc4);
            As[lc4+0][row] = av.x; As[lc4+1][row] = av.y;
            As[lc4+2][row] = av.z; As[lc4+3][row] = av.w;
            float4 bv = *(const float4*)(W + (size_t)(n0 + row) * Kdim + k0 + lc4);
            Bs[lc4+0][row] = bv.x; Bs[lc4+1][row] = bv.y;
            Bs[lc4+2][row] = bv.z; Bs[lc4+3][row] = bv.w;
        }
        __syncthreads();
#pragma unroll
        for (int kk = 0; kk < 16; kk++) {
            float a[8], b[8];
            *(float4*)&a[0] = *(const float4*)&As[kk][ty*8];
            *(float4*)&a[4] = *(const float4*)&As[kk][ty*8 + 4];
            *(float4*)&b[0] = *(const float4*)&Bs[kk][tx*8];
            *(float4*)&b[4] = *(const float4*)&Bs[kk][tx*8 + 4];
#pragma unroll
            for (int i = 0; i < 8; i++)
#pragma unroll
                for (int j = 0; j < 8; j++)
                    acc[i][j] = fmaf(a[i], b[j], acc[i][j]);
        }
        __syncthreads();
    }

#pragma unroll
    for (int i = 0; i < 8; i++) {
        const int m = m0 + ty*8 + i;
#pragma unroll
        for (int jj = 0; jj < 2; jj++) {
            const int n = n0 + tx*8 + jj*4;
            float4 bb = *(const float4*)(bias + n);
            float4 o;
            o.x = acc[i][jj*4+0] + bb.x;
            o.y = acc[i][jj*4+1] + bb.y;
            o.z = acc[i][jj*4+2] + bb.z;
            o.w = acc[i][jj*4+3] + bb.w;
            if (SCATTER) {
                const int b_  = m >> 11;      // m / S
                const int s_  = m & (Sdim-1);
                const int h_  = n >> 6;       // n / DK
                const int dk_ = n & (DKdim-1);
                *(float4*)(Cout + (((size_t)(b_*Hdim + h_) * Sdim + s_) * DKdim + dk_)) = o;
            } else {
                *(float4*)(Cout + (size_t)m * Ddim + n) = o;
            }
        }
    }
}

// ---------------------------------------------------------------------------
// Flash attention (fp32): per CTA = one (b,h) and 64 q rows.
// Streams 32 tiles of 64 K/V rows. 4x4 microtile for both GEMMs.
// ---------------------------------------------------------------------------
#define AP 68   // smem pitch (floats): 16B-aligned rows, conflict-aware

__global__ void __launch_bounds__(256)
attn_kernel(const float* __restrict__ Q, const float* __restrict__ Kg,
            const float* __restrict__ Vg, float* __restrict__ ctx)
{
    extern __shared__ float smf[];
    float* Qs = smf;                 // [64][AP]  natural: [qrow][d]
    float* KP = smf + 64 * AP;       // K transposed [d][kcol]; reused as P [qrow][kcol]
    float* Vs = smf + 128 * AP;      // [kcol][d] natural

    const int tid = threadIdx.x;
    const int tx = tid & 15, ty = tid >> 4;
    const int bh = blockIdx.y;             // 0..63
    const int b  = bh >> 4, h = bh & 15;
    const int q0 = blockIdx.x * 64;

    const float* Qp = Q  + ((size_t)bh * Sdim + q0) * DKdim;
    const float* Kp = Kg + (size_t)bh * Sdim * DKdim;
    const float* Vp = Vg + (size_t)bh * Sdim * DKdim;

    // Load Q tile, pre-scaled by 1/sqrt(dk)
#pragma unroll
    for (int t = 0; t < 4; t++) {
        const int f   = tid + 256 * t;
        const int row = f >> 4;
        const int c4  = (f & 15) << 2;
        float4 v = *(const float4*)(Qp + row * DKdim + c4);
        v.x *= 0.125f; v.y *= 0.125f; v.z *= 0.125f; v.w *= 0.125f;
        *(float4*)&Qs[row * AP + c4] = v;
    }

    float o[4][4];
#pragma unroll
    for (int i = 0; i < 4; i++)
#pragma unroll
        for (int j = 0; j < 4; j++) o[i][j] = 0.f;
    float mrow[4], lsum[4];
#pragma unroll
    for (int i = 0; i < 4; i++) { mrow[i] = -1e30f; lsum[i] = 0.f; }

    for (int kt = 0; kt < Sdim / 64; kt++) {
        __syncthreads();   // previous iteration done with KP(P)/Vs
        const float* Kt = Kp + kt * 64 * DKdim;
        const float* Vt = Vp + kt * 64 * DKdim;
#pragma unroll
        for (int t = 0; t < 4; t++) {
            const int f   = tid + 256 * t;
            const int col = f >> 4;          // k-position within tile
            const int c4  = (f & 15) << 2;   // d
            float4 kv = *(const float4*)(Kt + col * DKdim + c4);
            KP[(c4+0)*AP + col] = kv.x;
            KP[(c4+1)*AP + col] = kv.y;
            KP[(c4+2)*AP + col] = kv.z;
            KP[(c4+3)*AP + col] = kv.w;
            float4 vv = *(const float4*)(Vt + col * DKdim + c4);
            *(float4*)&Vs[col * AP + c4] = vv;
        }
        __syncthreads();

        // S = Q K^T  (rows ty*4+i, cols tx*4+j)
        float sv[4][4];
#pragma unroll
        for (int i = 0; i < 4; i++)
#pragma unroll
            for (int j = 0; j < 4; j++) sv[i][j] = 0.f;
#pragma unroll 8
        for (int d = 0; d < 64; d++) {
            float a[4];
#pragma unroll
            for (int i = 0; i < 4; i++) a[i] = Qs[(ty*4+i)*AP + d];
            float4 b4 = *(const float4*)&KP[d*AP + tx*4];
            const float bb[4] = {b4.x, b4.y, b4.z, b4.w};
#pragma unroll
            for (int i = 0; i < 4; i++)
#pragma unroll
                for (int j = 0; j < 4; j++)
                    sv[i][j] = fmaf(a[i], bb[j], sv[i][j]);
        }

        // Online softmax update
        float pr[4][4];
#pragma unroll
        for (int i = 0; i < 4; i++) {
            float tm = fmaxf(fmaxf(sv[i][0], sv[i][1]), fmaxf(sv[i][2], sv[i][3]));
            tm = fmaxf(tm, __shfl_xor_sync(0xffffffffu, tm, 1));
            tm = fmaxf(tm, __shfl_xor_sync(0xffffffffu, tm, 2));
            tm = fmaxf(tm, __shfl_xor_sync(0xffffffffu, tm, 4));
            tm = fmaxf(tm, __shfl_xor_sync(0xffffffffu, tm, 8));
            const float mnew  = fmaxf(mrow[i], tm);
            const float alpha = __expf(mrow[i] - mnew);
            mrow[i] = mnew;
            float rs = 0.f;
#pragma unroll
            for (int j = 0; j < 4; j++) {
                pr[i][j] = __expf(sv[i][j] - mnew);
                rs += pr[i][j];
            }
            rs += __shfl_xor_sync(0xffffffffu, rs, 1);
            rs += __shfl_xor_sync(0xffffffffu, rs, 2);
            rs += __shfl_xor_sync(0xffffffffu, rs, 4);
            rs += __shfl_xor_sync(0xffffffffu, rs, 8);
            lsum[i] = lsum[i] * alpha + rs;
#pragma unroll
            for (int j = 0; j < 4; j++) o[i][j] *= alpha;
        }

        __syncthreads();   // all threads done reading KP as K
#pragma unroll
        for (int i = 0; i < 4; i++)
#pragma unroll
            for (int j = 0; j < 4; j++)
                KP[(ty*4+i)*AP + tx*4 + j] = pr[i][j];
        __syncthreads();

        // O += P @ V   (o cols = dk dims tx*4+j)
#pragma unroll 8
        for (int k = 0; k < 64; k++) {
            float a[4];
#pragma unroll
            for (int i = 0; i < 4; i++) a[i] = KP[(ty*4+i)*AP + k];
            float4 b4 = *(const float4*)&Vs[k*AP + tx*4];
            const float bb[4] = {b4.x, b4.y, b4.z, b4.w};
#pragma unroll
            for (int i = 0; i < 4; i++)
#pragma unroll
                for (int j = 0; j < 4; j++)
                    o[i][j] = fmaf(a[i], bb[j], o[i][j]);
        }
    }

    // Epilogue: normalize, write ctx in [b,s,d] layout
#pragma unroll
    for (int i = 0; i < 4; i++) {
        const float inv = 1.f / lsum[i];
        const int srow = q0 + ty*4 + i;
        float4 ov;
        ov.x = o[i][0]*inv; ov.y = o[i][1]*inv;
        ov.z = o[i][2]*inv; ov.w = o[i][3]*inv;
        *(float4*)&ctx[((size_t)b * Sdim + srow) * Ddim + h * DKdim + tx*4] = ov;
    }
}

// ---------------------------------------------------------------------------
extern "C" void kernel_launch(void* const* d_in, const int* in_sizes, int n_in,
                              void* d_out, int out_size)
{
    (void)in_sizes; (void)n_in; (void)out_size;
    const float* x  = (const float*)d_in[0];
    // d_in[1] = attention_mask (unused by the reference forward)
    const float* Wq = (const float*)d_in[2];
    const float* bq = (const float*)d_in[3];
    const float* Wk = (const float*)d_in[4];
    const float* bk = (const float*)d_in[5];
    const float* Wv = (const float*)d_in[6];
    const float* bv = (const float*)d_in[7];
    const float* Wo = (const float*)d_in[8];
    const float* bo = (const float*)d_in[9];
    float* out = (float*)d_out;

    float *Qb, *Kb, *Vb, *Cb;
    cudaGetSymbolAddress((void**)&Qb, g_Q);
    cudaGetSymbolAddress((void**)&Kb, g_K);
    cudaGetSymbolAddress((void**)&Vb, g_V);
    cudaGetSymbolAddress((void**)&Cb, g_ctx);

    const dim3 gg(Ddim / 128, Mtot / 128);   // (8, 64)
    gemm_kernel<true><<<gg, 256>>>(x, Wq, bq, Qb, Ddim);
    gemm_kernel<true><<<gg, 256>>>(x, Wk, bk, Kb, Ddim);
    gemm_kernel<true><<<gg, 256>>>(x, Wv, bv, Vb, Ddim);

    const int ATTN_SMEM = 3 * 64 * AP * (int)sizeof(float);   // 52224 B
    cudaFuncSetAttribute(attn_kernel,
                         cudaFuncAttributeMaxDynamicSharedMemorySize, ATTN_SMEM);
    attn_kernel<<<dim3(Sdim / 64, Bdim * Hdim), 256, ATTN_SMEM>>>(Qb, Kb, Vb, Cb);

    gemm_kernel<false><<<gg, 256>>>(Cb, Wo, bo, out, Ddim);
}

// round 2
// speedup vs baseline: 3.0280x; 3.0280x over previous
#include <cuda_runtime.h>
#include <math.h>
#include <stdint.h>

#define Bdim 4
#define Sdim 2048
#define Ddim 1024
#define Hdim 16
#define DKdim 64
#define Mtot (Bdim*Sdim)   // 8192

// Scratch (device globals: sanctioned no-alloc workaround)
__device__ float g_Q[Bdim*Hdim*Sdim*DKdim];   // [b,h,s,dk]
__device__ float g_K[Bdim*Hdim*Sdim*DKdim];
__device__ float g_V[Bdim*Hdim*Sdim*DKdim];
__device__ float g_ctx[Bdim*Sdim*Ddim];       // [b,s,d]

// ---------------------------------------------------------------------------
// helpers
// ---------------------------------------------------------------------------
__device__ __forceinline__ uint32_t f2tf32(float f) {
    uint32_t u;
    asm("cvt.rna.tf32.f32 %0, %1;" : "=r"(u) : "f"(f));
    return u;
}

__device__ __forceinline__ void mma_tf32(float c[4], const uint32_t a[4], const uint32_t b[2]) {
    asm volatile(
        "mma.sync.aligned.m16n8k8.row.col.f32.tf32.tf32.f32 "
        "{%0,%1,%2,%3},{%4,%5,%6,%7},{%8,%9},{%0,%1,%2,%3};"
        : "+f"(c[0]), "+f"(c[1]), "+f"(c[2]), "+f"(c[3])
        : "r"(a[0]), "r"(a[1]), "r"(a[2]), "r"(a[3]), "r"(b[0]), "r"(b[1]));
}

__device__ __forceinline__ void cp16(uint32_t dst, const void* src) {
    asm volatile("cp.async.cg.shared.global [%0], [%1], 16;" :: "r"(dst), "l"(src));
}

// ---------------------------------------------------------------------------
// TF32 tensor-core GEMM-NT: C[m,n] = sum_k A[m,k]*W[n,k] + bias[n]
// A:[M,1024] rm, W:[N,1024] rm. BM=BN=128, BK=32, 256 thr, warp=64x32.
// SCATTER: write to [b,h,s,dk] layout (QKV proj); else [m,n].
// ---------------------------------------------------------------------------
#define GP 36            // smem pitch (floats); GP%32==4 -> conflict-free frags
#define GBUF (128*GP)    // one buffer (A or B), floats

template<bool SCATTER>
__global__ void __launch_bounds__(256, 2)
gemm_tc(const float* __restrict__ A, const float* __restrict__ W,
        const float* __restrict__ bias, float* __restrict__ Cout)
{
    extern __shared__ float sm[];
    float* As = sm;              // [2][128][GP]
    float* Bs = sm + 2*GBUF;     // [2][128][GP]

    const int tid  = threadIdx.x;
    const int lane = tid & 31, warp = tid >> 5;
    const int wm   = warp >> 2, wn = warp & 3;
    const int m0   = blockIdx.y * 128, n0 = blockIdx.x * 128;

    float c[4][4][4];
#pragma unroll
    for (int i = 0; i < 4; i++)
#pragma unroll
        for (int j = 0; j < 4; j++)
#pragma unroll
            for (int t = 0; t < 4; t++) c[i][j][t] = 0.f;

    const int lr = tid >> 3;         // 0..31
    const int lc = (tid & 7) * 4;    // 0,4,...,28

#define GEMM_PREFETCH(kt, buf) do {                                          \
        const float* Ag_ = A + (size_t)m0 * 1024 + (kt) * 32;                \
        const float* Wg_ = W + (size_t)n0 * 1024 + (kt) * 32;                \
        uint32_t asb_ = (uint32_t)__cvta_generic_to_shared(As + (buf)*GBUF); \
        uint32_t bsb_ = (uint32_t)__cvta_generic_to_shared(Bs + (buf)*GBUF); \
        _Pragma("unroll")                                                    \
        for (int p_ = 0; p_ < 4; p_++) {                                     \
            int row_ = lr + p_ * 32;                                         \
            cp16(asb_ + (row_*GP + lc)*4, Ag_ + (size_t)row_*1024 + lc);     \
            cp16(bsb_ + (row_*GP + lc)*4, Wg_ + (size_t)row_*1024 + lc);     \
        }                                                                    \
        asm volatile("cp.async.commit_group;");                              \
    } while (0)

    GEMM_PREFETCH(0, 0);

    for (int kt = 0; kt < 32; kt++) {
        if (kt + 1 < 32) {
            GEMM_PREFETCH(kt + 1, (kt + 1) & 1);
            asm volatile("cp.async.wait_group 1;");
        } else {
            asm volatile("cp.async.wait_group 0;");
        }
        __syncthreads();

        const float* Ab = As + (kt & 1) * GBUF + (wm * 64) * GP;
        const float* Bb = Bs + (kt & 1) * GBUF + (wn * 32) * GP;

#pragma unroll
        for (int ks = 0; ks < 4; ks++) {
            uint32_t a[4][4], b[4][2];
#pragma unroll
            for (int i = 0; i < 4; i++) {
                const float* ap = Ab + (i*16 + (lane >> 2)) * GP + ks*8 + (lane & 3);
                a[i][0] = f2tf32(ap[0]);
                a[i][1] = f2tf32(ap[8*GP]);
                a[i][2] = f2tf32(ap[4]);
                a[i][3] = f2tf32(ap[8*GP + 4]);
            }
#pragma unroll
            for (int j = 0; j < 4; j++) {
                const float* bp = Bb + (j*8 + (lane >> 2)) * GP + ks*8 + (lane & 3);
                b[j][0] = f2tf32(bp[0]);
                b[j][1] = f2tf32(bp[4]);
            }
#pragma unroll
            for (int i = 0; i < 4; i++)
#pragma unroll
                for (int j = 0; j < 4; j++)
                    mma_tf32(c[i][j], a[i], b[j]);
        }
        __syncthreads();
    }

    // epilogue
#pragma unroll
    for (int i = 0; i < 4; i++) {
        const int r0 = m0 + wm*64 + i*16 + (lane >> 2);
#pragma unroll
        for (int j = 0; j < 4; j++) {
            const int n = n0 + wn*32 + j*8 + 2*(lane & 3);
            const float2 bb = *(const float2*)(bias + n);
            float2 v0 = make_float2(c[i][j][0] + bb.x, c[i][j][1] + bb.y);
            float2 v1 = make_float2(c[i][j][2] + bb.x, c[i][j][3] + bb.y);
            if (SCATTER) {
                const int h_  = n >> 6, dk_ = n & 63;
                const int b_  = r0 >> 11, s_ = r0 & 2047;   // r0,r0+8 same b-block
                float* base = Cout + (((size_t)(b_*Hdim + h_) * Sdim + s_) * DKdim + dk_);
                *(float2*)base = v0;
                *(float2*)(base + 8 * DKdim) = v1;
            } else {
                *(float2*)(Cout + (size_t)r0 * 1024 + n) = v0;
                *(float2*)(Cout + (size_t)(r0 + 8) * 1024 + n) = v1;
            }
        }
    }
}

// ---------------------------------------------------------------------------
// Flash attention on tf32 tensor cores.
// CTA = one (b,h) x 128 q rows. 8 warps, each owns a 16-row stripe
// (full rows -> softmax reduction is a 4-lane shfl, P stays warp-local).
// K-tiles of 64 positions streamed through smem in natural layout.
// ---------------------------------------------------------------------------
#define QP 68   // pitch for Qs/Ks/Ps: 68%32==4 -> A-frag & K-B-frag conflict-free
#define VP 72   // pitch for Vs: 72%32==8 -> V-B-frag conflict-free

__global__ void __launch_bounds__(256)
attn_tc(const float* __restrict__ Q, const float* __restrict__ Kg,
        const float* __restrict__ Vg, float* __restrict__ ctx)
{
    extern __shared__ float sm[];
    float* Qs = sm;                       // [128][QP]   (q row, dk) pre-scaled
    float* Ks = Qs + 128*QP;              // [64][QP]    (kpos, dk) natural
    float* Vs = Ks + 64*QP;               // [64][VP]    (kpos, dk) natural
    float* Ps = Vs + 64*VP;               // [128][QP]   (q row, kpos)

    const int tid  = threadIdx.x;
    const int lane = tid & 31, warp = tid >> 5;
    const int bh = blockIdx.y;            // b*16+h
    const int b  = bh >> 4, h = bh & 15;
    const int q0 = blockIdx.x * 128;

    const float* Qp = Q  + ((size_t)bh * Sdim + q0) * DKdim;
    const float* Kp = Kg + (size_t)bh * Sdim * DKdim;
    const float* Vp = Vg + (size_t)bh * Sdim * DKdim;

    // Load Q tile, pre-scaled by 1/sqrt(dk)=0.125
    for (int idx = tid; idx < 128*16; idx += 256) {
        const int row = idx >> 4, c4 = (idx & 15) << 2;
        float4 v = *(const float4*)(Qp + row * DKdim + c4);
        v.x *= 0.125f; v.y *= 0.125f; v.z *= 0.125f; v.w *= 0.125f;
        *(float4*)&Qs[row * QP + c4] = v;
    }

    float o[8][4];
#pragma unroll
    for (int j = 0; j < 8; j++)
#pragma unroll
        for (int t = 0; t < 4; t++) o[j][t] = 0.f;
    float mrow[2] = {-1e30f, -1e30f};
    float lsum[2] = {0.f, 0.f};

    const int rA = warp*16 + (lane >> 2);    // A-frag row (q) for this thread
    const int cL = lane & 3;                 // k-lane within frag
    const int nL = lane >> 2;                // n-lane within frag

    for (int kt = 0; kt < Sdim/64; kt++) {
        __syncthreads();   // previous iter done reading Ks/Vs (and Q load on kt==0)
        const float* Kt = Kp + kt * 64 * DKdim;
        const float* Vt = Vp + kt * 64 * DKdim;
        for (int idx = tid; idx < 64*16; idx += 256) {
            const int row = idx >> 4, c4 = (idx & 15) << 2;
            *(float4*)&Ks[row * QP + c4] = *(const float4*)(Kt + row * DKdim + c4);
            *(float4*)&Vs[row * VP + c4] = *(const float4*)(Vt + row * DKdim + c4);
        }
        __syncthreads();

        // ---- S = Q K^T : warp rows [warp*16, warp*16+16), cols 0..63 ----
        float s[8][4];
#pragma unroll
        for (int j = 0; j < 8; j++)
#pragma unroll
            for (int t = 0; t < 4; t++) s[j][t] = 0.f;

#pragma unroll
        for (int ks = 0; ks < 8; ks++) {
            uint32_t a[4];
            const float* qp = Qs + rA * QP + ks*8 + cL;
            a[0] = f2tf32(qp[0]);
            a[1] = f2tf32(qp[8*QP]);
            a[2] = f2tf32(qp[4]);
            a[3] = f2tf32(qp[8*QP + 4]);
#pragma unroll
            for (int j = 0; j < 8; j++) {
                const float* kp = Ks + (j*8 + nL) * QP + ks*8 + cL;
                uint32_t bfr[2] = { f2tf32(kp[0]), f2tf32(kp[4]) };
                mma_tf32(s[j], a, bfr);
            }
        }

        // ---- online softmax (rows lane>>2 and lane>>2+8 of warp stripe) ----
#pragma unroll
        for (int hh = 0; hh < 2; hh++) {
            float tm = -1e30f;
#pragma unroll
            for (int j = 0; j < 8; j++)
                tm = fmaxf(tm, fmaxf(s[j][hh*2], s[j][hh*2+1]));
            tm = fmaxf(tm, __shfl_xor_sync(0xffffffffu, tm, 1));
            tm = fmaxf(tm, __shfl_xor_sync(0xffffffffu, tm, 2));
            const float mnew  = fmaxf(mrow[hh], tm);
            const float alpha = __expf(mrow[hh] - mnew);
            mrow[hh] = mnew;
            float rs = 0.f;
#pragma unroll
            for (int j = 0; j < 8; j++) {
                const float p0 = __expf(s[j][hh*2]   - mnew);
                const float p1 = __expf(s[j][hh*2+1] - mnew);
                s[j][hh*2] = p0; s[j][hh*2+1] = p1;
                rs += p0 + p1;
            }
            rs += __shfl_xor_sync(0xffffffffu, rs, 1);
            rs += __shfl_xor_sync(0xffffffffu, rs, 2);
            lsum[hh] = lsum[hh] * alpha + rs;
#pragma unroll
            for (int j = 0; j < 8; j++) {
                o[j][hh*2]   *= alpha;
                o[j][hh*2+1] *= alpha;
            }
        }

        // ---- P to smem (warp-local rows only) ----
#pragma unroll
        for (int j = 0; j < 8; j++) {
#pragma unroll
            for (int hh = 0; hh < 2; hh++) {
                *(float2*)&Ps[(rA + hh*8) * QP + j*8 + 2*cL] =
                    make_float2(s[j][hh*2], s[j][hh*2+1]);
            }
        }
        __syncwarp();

        // ---- O += P V : A = P (k=kpos), B = V natural [kpos][dk] ----
#pragma unroll
        for (int ks = 0; ks < 8; ks++) {
            uint32_t a[4];
            const float* pp = Ps + rA * QP + ks*8 + cL;
            a[0] = f2tf32(pp[0]);
            a[1] = f2tf32(pp[8*QP]);
            a[2] = f2tf32(pp[4]);
            a[3] = f2tf32(pp[8*QP + 4]);
#pragma unroll
            for (int j = 0; j < 8; j++) {
                const float* vp = Vs + (ks*8 + cL) * VP + j*8 + nL;
                uint32_t bfr[2] = { f2tf32(vp[0]), f2tf32(vp[4*VP]) };
                mma_tf32(o[j], a, bfr);
            }
        }
    }

    // ---- epilogue: normalize, write ctx [b,s,d] ----
    const float inv0 = 1.f / lsum[0];
    const float inv1 = 1.f / lsum[1];
#pragma unroll
    for (int hh = 0; hh < 2; hh++) {
        const float inv = hh ? inv1 : inv0;
        const int srow = q0 + rA + hh*8;
        float* base = ctx + ((size_t)b * Sdim + srow) * Ddim + h * DKdim;
#pragma unroll
        for (int j = 0; j < 8; j++) {
            *(float2*)(base + j*8 + 2*cL) =
                make_float2(o[j][hh*2] * inv, o[j][hh*2+1] * inv);
        }
    }
}

// ---------------------------------------------------------------------------
extern "C" void kernel_launch(void* const* d_in, const int* in_sizes, int n_in,
                              void* d_out, int out_size)
{
    (void)in_sizes; (void)n_in; (void)out_size;
    const float* x  = (const float*)d_in[0];
    // d_in[1] = attention_mask (unused by reference forward)
    const float* Wq = (const float*)d_in[2];
    const float* bq = (const float*)d_in[3];
    const float* Wk = (const float*)d_in[4];
    const float* bk = (const float*)d_in[5];
    const float* Wv = (const float*)d_in[6];
    const float* bv = (const float*)d_in[7];
    const float* Wo = (const float*)d_in[8];
    const float* bo = (const float*)d_in[9];
    float* out = (float*)d_out;

    float *Qb, *Kb, *Vb, *Cb;
    cudaGetSymbolAddress((void**)&Qb, g_Q);
    cudaGetSymbolAddress((void**)&Kb, g_K);
    cudaGetSymbolAddress((void**)&Vb, g_V);
    cudaGetSymbolAddress((void**)&Cb, g_ctx);

    const int GEMM_SMEM = 4 * GBUF * (int)sizeof(float);               // 73728
    const int ATTN_SMEM = (320 * QP + 64 * VP) * (int)sizeof(float);   // 105472

    static int configured = 0;
    if (!configured) {
        cudaFuncSetAttribute(gemm_tc<true>,
                             cudaFuncAttributeMaxDynamicSharedMemorySize, GEMM_SMEM);
        cudaFuncSetAttribute(gemm_tc<false>,
                             cudaFuncAttributeMaxDynamicSharedMemorySize, GEMM_SMEM);
        cudaFuncSetAttribute(attn_tc,
                             cudaFuncAttributeMaxDynamicSharedMemorySize, ATTN_SMEM);
        configured = 1;
    }

    const dim3 gg(Ddim / 128, Mtot / 128);   // (8, 64)
    gemm_tc<true><<<gg, 256, GEMM_SMEM>>>(x, Wq, bq, Qb);
    gemm_tc<true><<<gg, 256, GEMM_SMEM>>>(x, Wk, bk, Kb);
    gemm_tc<true><<<gg, 256, GEMM_SMEM>>>(x, Wv, bv, Vb);

    attn_tc<<<dim3(Sdim / 128, Bdim * Hdim), 256, ATTN_SMEM>>>(Qb, Kb, Vb, Cb);

    gemm_tc<false><<<gg, 256, GEMM_SMEM>>>(Cb, Wo, bo, out);
}

// round 4
// speedup vs baseline: 3.1381x; 1.0363x over previous
#include <cuda_runtime.h>
#include <math.h>
#include <stdint.h>

#define Bdim 4
#define Sdim 2048
#define Ddim 1024
#define Hdim 16
#define DKdim 64
#define Mtot (Bdim*Sdim)   // 8192

// Scratch (device globals: sanctioned no-alloc workaround)
__device__ float g_Q[Bdim*Hdim*Sdim*DKdim];   // [b,h,s,dk] tf32-rounded
__device__ float g_K[Bdim*Hdim*Sdim*DKdim];   // tf32-rounded
__device__ float g_V[Bdim*Hdim*Sdim*DKdim];   // tf32-rounded
__device__ float g_ctx[Bdim*Sdim*Ddim];       // [b,s,d] tf32-rounded
__device__ float g_xr[Mtot*Ddim];             // tf32-rounded encoder input
__device__ float g_wr[4*Ddim*Ddim];           // tf32-rounded Wq,Wk,Wv,Wo

// ---------------------------------------------------------------------------
__device__ __forceinline__ uint32_t f2tf32(float f) {
    uint32_t u;
    asm("cvt.rna.tf32.f32 %0, %1;" : "=r"(u) : "f"(f));
    return u;
}

__device__ __forceinline__ void mma_tf32(float c[4], const uint32_t a[4], const uint32_t b[2]) {
    asm volatile(
        "mma.sync.aligned.m16n8k8.row.col.f32.tf32.tf32.f32 "
        "{%0,%1,%2,%3},{%4,%5,%6,%7},{%8,%9},{%0,%1,%2,%3};"
        : "+f"(c[0]), "+f"(c[1]), "+f"(c[2]), "+f"(c[3])
        : "r"(a[0]), "r"(a[1]), "r"(a[2]), "r"(a[3]), "r"(b[0]), "r"(b[1]));
}

__device__ __forceinline__ void cp16(uint32_t dst, const void* src) {
    asm volatile("cp.async.cg.shared.global [%0], [%1], 16;" :: "r"(dst), "l"(src));
}

// ---------------------------------------------------------------------------
// Elementwise tf32 rounding pass (float4 granularity)
// ---------------------------------------------------------------------------
__global__ void round_tf32_kernel(const float* __restrict__ in,
                                  float* __restrict__ out, int n4)
{
    int i = blockIdx.x * 256 + threadIdx.x;
    if (i < n4) {
        float4 v = ((const float4*)in)[i];
        v.x = __uint_as_float(f2tf32(v.x));
        v.y = __uint_as_float(f2tf32(v.y));
        v.z = __uint_as_float(f2tf32(v.z));
        v.w = __uint_as_float(f2tf32(v.w));
        ((float4*)out)[i] = v;
    }
}

// ---------------------------------------------------------------------------
// TF32 tensor-core GEMM-NT on pre-rounded inputs:
// C[m,n] = sum_k A[m,k]*W[n,k] + bias[n]
// SCATTER: write tf32-rounded to [b,h,s,dk] (QKV proj); else plain [m,n].
// ---------------------------------------------------------------------------
#define GP 36            // smem pitch (floats); GP%32==4 -> conflict-free frags
#define GBUF (128*GP)    // one buffer (A or B), floats

template<bool SCATTER>
__global__ void __launch_bounds__(256, 2)
gemm_tc(const float* __restrict__ A, const float* __restrict__ W,
        const float* __restrict__ bias, float* __restrict__ Cout)
{
    extern __shared__ float sm[];
    float* As = sm;              // [2][128][GP]
    float* Bs = sm + 2*GBUF;     // [2][128][GP]

    const int tid  = threadIdx.x;
    const int lane = tid & 31, warp = tid >> 5;
    const int wm   = warp >> 2, wn = warp & 3;
    const int m0   = blockIdx.y * 128, n0 = blockIdx.x * 128;

    float c[4][4][4];
#pragma unroll
    for (int i = 0; i < 4; i++)
#pragma unroll
        for (int j = 0; j < 4; j++)
#pragma unroll
            for (int t = 0; t < 4; t++) c[i][j][t] = 0.f;

    const int lr = tid >> 3;         // 0..31
    const int lc = (tid & 7) * 4;    // 0,4,...,28

#define GEMM_PREFETCH(kt, bufsel) do {                                          \
        const float* Ag_ = A + (size_t)m0 * 1024 + (kt) * 32;                   \
        const float* Wg_ = W + (size_t)n0 * 1024 + (kt) * 32;                   \
        uint32_t asb_ = (uint32_t)__cvta_generic_to_shared(As + (bufsel)*GBUF); \
        uint32_t bsb_ = (uint32_t)__cvta_generic_to_shared(Bs + (bufsel)*GBUF); \
        _Pragma("unroll")                                                       \
        for (int p_ = 0; p_ < 4; p_++) {                                        \
            int row_ = lr + p_ * 32;                                            \
            cp16(asb_ + (row_*GP + lc)*4, Ag_ + (size_t)row_*1024 + lc);        \
            cp16(bsb_ + (row_*GP + lc)*4, Wg_ + (size_t)row_*1024 + lc);        \
        }                                                                       \
        asm volatile("cp.async.commit_group;");                                 \
    } while (0)

    GEMM_PREFETCH(0, 0);

    for (int kt = 0; kt < 32; kt++) {
        if (kt + 1 < 32) {
            GEMM_PREFETCH(kt + 1, (kt + 1) & 1);
            asm volatile("cp.async.wait_group 1;");
        } else {
            asm volatile("cp.async.wait_group 0;");
        }
        __syncthreads();

        const float* Ab = As + (kt & 1) * GBUF + (wm * 64) * GP;
        const float* Bb = Bs + (kt & 1) * GBUF + (wn * 32) * GP;

#pragma unroll
        for (int ks = 0; ks < 4; ks++) {
            uint32_t a[4][4], b[4][2];
#pragma unroll
            for (int i = 0; i < 4; i++) {
                const float* ap = Ab + (i*16 + (lane >> 2)) * GP + ks*8 + (lane & 3);
                a[i][0] = __float_as_uint(ap[0]);
                a[i][1] = __float_as_uint(ap[8*GP]);
                a[i][2] = __float_as_uint(ap[4]);
                a[i][3] = __float_as_uint(ap[8*GP + 4]);
            }
#pragma unroll
            for (int j = 0; j < 4; j++) {
                const float* bp = Bb + (j*8 + (lane >> 2)) * GP + ks*8 + (lane & 3);
                b[j][0] = __float_as_uint(bp[0]);
                b[j][1] = __float_as_uint(bp[4]);
            }
#pragma unroll
            for (int i = 0; i < 4; i++)
#pragma unroll
                for (int j = 0; j < 4; j++)
                    mma_tf32(c[i][j], a[i], b[j]);
        }
        __syncthreads();
    }

    // epilogue
#pragma unroll
    for (int i = 0; i < 4; i++) {
        const int r0 = m0 + wm*64 + i*16 + (lane >> 2);
#pragma unroll
        for (int j = 0; j < 4; j++) {
            const int n = n0 + wn*32 + j*8 + 2*(lane & 3);
            const float2 bb = *(const float2*)(bias + n);
            if (SCATTER) {
                float2 v0, v1;
                v0.x = __uint_as_float(f2tf32(c[i][j][0] + bb.x));
                v0.y = __uint_as_float(f2tf32(c[i][j][1] + bb.y));
                v1.x = __uint_as_float(f2tf32(c[i][j][2] + bb.x));
                v1.y = __uint_as_float(f2tf32(c[i][j][3] + bb.y));
                const int h_  = n >> 6, dk_ = n & 63;
                const int b_  = r0 >> 11, s_ = r0 & 2047;
                float* base = Cout + (((size_t)(b_*Hdim + h_) * Sdim + s_) * DKdim + dk_);
                *(float2*)base = v0;
                *(float2*)(base + 8 * DKdim) = v1;
            } else {
                float2 v0 = make_float2(c[i][j][0] + bb.x, c[i][j][1] + bb.y);
                float2 v1 = make_float2(c[i][j][2] + bb.x, c[i][j][3] + bb.y);
                *(float2*)(Cout + (size_t)r0 * 1024 + n) = v0;
                *(float2*)(Cout + (size_t)(r0 + 8) * 1024 + n) = v1;
            }
        }
    }
}

// ---------------------------------------------------------------------------
// Flash attention on tf32 tensor cores (pre-rounded Q/K/V, zero inner cvts).
// CTA = one (b,h) x 128 q rows. 8 warps, each owns a 16-row stripe.
// Identical structure to the round-2 (verified) kernel.
// ---------------------------------------------------------------------------
#define QP 68   // pitch for Qs/Ks/Ps: 68%32==4 -> A-frag & K-B-frag conflict-free
#define VP 72   // pitch for Vs: 72%32==8 -> V-B-frag conflict-free

__global__ void __launch_bounds__(256)
attn_tc(const float* __restrict__ Q, const float* __restrict__ Kg,
        const float* __restrict__ Vg, float* __restrict__ ctx)
{
    extern __shared__ float sm[];
    float* Qs = sm;                       // [128][QP]   (q row, dk) pre-scaled
    float* Ks = Qs + 128*QP;              // [64][QP]    (kpos, dk) natural
    float* Vs = Ks + 64*QP;               // [64][VP]    (kpos, dk) natural
    float* Ps = Vs + 64*VP;               // [128][QP]   (q row, kpos)

    const int tid  = threadIdx.x;
    const int lane = tid & 31, warp = tid >> 5;
    const int bh = blockIdx.y;            // b*16+h
    const int b  = bh >> 4, h = bh & 15;
    const int q0 = blockIdx.x * 128;

    const float* Qp = Q  + ((size_t)bh * Sdim + q0) * DKdim;
    const float* Kp = Kg + (size_t)bh * Sdim * DKdim;
    const float* Vp = Vg + (size_t)bh * Sdim * DKdim;

    // Load Q tile, scale by 1/sqrt(dk)=0.125 (exact power of 2: stays tf32)
    for (int idx = tid; idx < 128*16; idx += 256) {
        const int row = idx >> 4, c4 = (idx & 15) << 2;
        float4 v = *(const float4*)(Qp + row * DKdim + c4);
        v.x *= 0.125f; v.y *= 0.125f; v.z *= 0.125f; v.w *= 0.125f;
        *(float4*)&Qs[row * QP + c4] = v;
    }

    float o[8][4];
#pragma unroll
    for (int j = 0; j < 8; j++)
#pragma unroll
        for (int t = 0; t < 4; t++) o[j][t] = 0.f;
    float mrow[2] = {-1e30f, -1e30f};
    float lsum[2] = {0.f, 0.f};

    const int rA = warp*16 + (lane >> 2);    // A-frag row (q) for this thread
    const int cL = lane & 3;                 // k-lane within frag
    const int nL = lane >> 2;                // n-lane within frag

    for (int kt = 0; kt < Sdim/64; kt++) {
        __syncthreads();   // previous iter done reading Ks/Vs (and Q load on kt==0)
        const float* Kt = Kp + kt * 64 * DKdim;
        const float* Vt = Vp + kt * 64 * DKdim;
        for (int idx = tid; idx < 64*16; idx += 256) {
            const int row = idx >> 4, c4 = (idx & 15) << 2;
            *(float4*)&Ks[row * QP + c4] = *(const float4*)(Kt + row * DKdim + c4);
            *(float4*)&Vs[row * VP + c4] = *(const float4*)(Vt + row * DKdim + c4);
        }
        __syncthreads();

        // ---- S = Q K^T : warp rows [warp*16, warp*16+16), cols 0..63 ----
        float s[8][4];
#pragma unroll
        for (int j = 0; j < 8; j++)
#pragma unroll
            for (int t = 0; t < 4; t++) s[j][t] = 0.f;

#pragma unroll
        for (int ks = 0; ks < 8; ks++) {
            uint32_t a[4];
            const float* qp = Qs + rA * QP + ks*8 + cL;
            a[0] = __float_as_uint(qp[0]);
            a[1] = __float_as_uint(qp[8*QP]);
            a[2] = __float_as_uint(qp[4]);
            a[3] = __float_as_uint(qp[8*QP + 4]);
#pragma unroll
            for (int j = 0; j < 8; j++) {
                const float* kp = Ks + (j*8 + nL) * QP + ks*8 + cL;
                uint32_t bfr[2] = { __float_as_uint(kp[0]), __float_as_uint(kp[4]) };
                mma_tf32(s[j], a, bfr);
            }
        }

        // ---- online softmax (rows lane>>2 and lane>>2+8 of warp stripe) ----
#pragma unroll
        for (int hh = 0; hh < 2; hh++) {
            float tm = -1e30f;
#pragma unroll
            for (int j = 0; j < 8; j++)
                tm = fmaxf(tm, fmaxf(s[j][hh*2], s[j][hh*2+1]));
            tm = fmaxf(tm, __shfl_xor_sync(0xffffffffu, tm, 1));
            tm = fmaxf(tm, __shfl_xor_sync(0xffffffffu, tm, 2));
            const float mnew  = fmaxf(mrow[hh], tm);
            const float alpha = __expf(mrow[hh] - mnew);
            mrow[hh] = mnew;
            float rs = 0.f;
#pragma unroll
            for (int j = 0; j < 8; j++) {
                const float p0 = __expf(s[j][hh*2]   - mnew);
                const float p1 = __expf(s[j][hh*2+1] - mnew);
                s[j][hh*2] = p0; s[j][hh*2+1] = p1;
                rs += p0 + p1;
            }
            rs += __shfl_xor_sync(0xffffffffu, rs, 1);
            rs += __shfl_xor_sync(0xffffffffu, rs, 2);
            lsum[hh] = lsum[hh] * alpha + rs;
#pragma unroll
            for (int j = 0; j < 8; j++) {
                o[j][hh*2]   *= alpha;
                o[j][hh*2+1] *= alpha;
            }
        }

        // ---- P -> smem, tf32-rounded at store (warp-local rows only) ----
#pragma unroll
        for (int j = 0; j < 8; j++) {
#pragma unroll
            for (int hh = 0; hh < 2; hh++) {
                float2 pv;
                pv.x = __uint_as_float(f2tf32(s[j][hh*2]));
                pv.y = __uint_as_float(f2tf32(s[j][hh*2+1]));
                *(float2*)&Ps[(rA + hh*8) * QP + j*8 + 2*cL] = pv;
            }
        }
        __syncwarp();

        // ---- O += P V : A = P (k=kpos), B = V natural [kpos][dk] ----
#pragma unroll
        for (int ks = 0; ks < 8; ks++) {
            uint32_t a[4];
            const float* pp = Ps + rA * QP + ks*8 + cL;
            a[0] = __float_as_uint(pp[0]);
            a[1] = __float_as_uint(pp[8*QP]);
            a[2] = __float_as_uint(pp[4]);
            a[3] = __float_as_uint(pp[8*QP + 4]);
#pragma unroll
            for (int j = 0; j < 8; j++) {
                const float* vp = Vs + (ks*8 + cL) * VP + j*8 + nL;
                uint32_t bfr[2] = { __float_as_uint(vp[0]), __float_as_uint(vp[4*VP]) };
                mma_tf32(o[j], a, bfr);
            }
        }
    }

    // ---- epilogue: normalize, round to tf32, write ctx [b,s,d] ----
    const float inv0 = 1.f / lsum[0];
    const float inv1 = 1.f / lsum[1];
#pragma unroll
    for (int hh = 0; hh < 2; hh++) {
        const float inv = hh ? inv1 : inv0;
        const int srow = q0 + rA + hh*8;
        float* base = ctx + ((size_t)b * Sdim + srow) * Ddim + h * DKdim;
#pragma unroll
        for (int j = 0; j < 8; j++) {
            float2 ov;
            ov.x = __uint_as_float(f2tf32(o[j][hh*2]   * inv));
            ov.y = __uint_as_float(f2tf32(o[j][hh*2+1] * inv));
            *(float2*)(base + j*8 + 2*cL) = ov;
        }
    }
}

// ---------------------------------------------------------------------------
extern "C" void kernel_launch(void* const* d_in, const int* in_sizes, int n_in,
                              void* d_out, int out_size)
{
    (void)in_sizes; (void)n_in; (void)out_size;
    const float* x  = (const float*)d_in[0];
    // d_in[1] = attention_mask (unused by reference forward)
    const float* Wq = (const float*)d_in[2];
    const float* bq = (const float*)d_in[3];
    const float* Wk = (const float*)d_in[4];
    const float* bk = (const float*)d_in[5];
    const float* Wv = (const float*)d_in[6];
    const float* bv = (const float*)d_in[7];
    const float* Wo = (const float*)d_in[8];
    const float* bo = (const float*)d_in[9];
    float* out = (float*)d_out;

    float *Qb, *Kb, *Vb, *Cb, *Xr, *Wr;
    cudaGetSymbolAddress((void**)&Qb, g_Q);
    cudaGetSymbolAddress((void**)&Kb, g_K);
    cudaGetSymbolAddress((void**)&Vb, g_V);
    cudaGetSymbolAddress((void**)&Cb, g_ctx);
    cudaGetSymbolAddress((void**)&Xr, g_xr);
    cudaGetSymbolAddress((void**)&Wr, g_wr);

    const int GEMM_SMEM = 4 * GBUF * (int)sizeof(float);               // 73728
    const int ATTN_SMEM = (320 * QP + 64 * VP) * (int)sizeof(float);   // 105472

    cudaFuncSetAttribute(gemm_tc<true>,
                         cudaFuncAttributeMaxDynamicSharedMemorySize, GEMM_SMEM);
    cudaFuncSetAttribute(gemm_tc<false>,
                         cudaFuncAttributeMaxDynamicSharedMemorySize, GEMM_SMEM);
    cudaFuncSetAttribute(attn_tc,
                         cudaFuncAttributeMaxDynamicSharedMemorySize, ATTN_SMEM);

    // tf32 pre-rounding passes (round once per element at the producer)
    round_tf32_kernel<<<(Mtot*Ddim/4 + 255)/256, 256>>>(x, Xr, Mtot*Ddim/4);
    round_tf32_kernel<<<(Ddim*Ddim/4 + 255)/256, 256>>>(Wq, Wr + 0*Ddim*Ddim, Ddim*Ddim/4);
    round_tf32_kernel<<<(Ddim*Ddim/4 + 255)/256, 256>>>(Wk, Wr + 1*Ddim*Ddim, Ddim*Ddim/4);
    round_tf32_kernel<<<(Ddim*Ddim/4 + 255)/256, 256>>>(Wv, Wr + 2*Ddim*Ddim, Ddim*Ddim/4);
    round_tf32_kernel<<<(Ddim*Ddim/4 + 255)/256, 256>>>(Wo, Wr + 3*Ddim*Ddim, Ddim*Ddim/4);

    const dim3 gg(Ddim / 128, Mtot / 128);   // (8, 64)
    gemm_tc<true><<<gg, 256, GEMM_SMEM>>>(Xr, Wr + 0*Ddim*Ddim, bq, Qb);
    gemm_tc<true><<<gg, 256, GEMM_SMEM>>>(Xr, Wr + 1*Ddim*Ddim, bk, Kb);
    gemm_tc<true><<<gg, 256, GEMM_SMEM>>>(Xr, Wr + 2*Ddim*Ddim, bv, Vb);

    attn_tc<<<dim3(Sdim / 128, Bdim * Hdim), 256, ATTN_SMEM>>>(Qb, Kb, Vb, Cb);

    gemm_tc<false><<<gg, 256, GEMM_SMEM>>>(Cb, Wr + 3*Ddim*Ddim, bo, out);
}

// round 6
// speedup vs baseline: 3.2959x; 1.0503x over previous
#include <cuda_runtime.h>
#include <math.h>
#include <stdint.h>

#define Bdim 4
#define Sdim 2048
#define Ddim 1024
#define Hdim 16
#define DKdim 64
#define Mtot (Bdim*Sdim)   // 8192

// Scratch (device globals: sanctioned no-alloc workaround)
__device__ float g_Q[Bdim*Hdim*Sdim*DKdim];   // [b,h,s,dk] tf32-rounded
__device__ float g_K[Bdim*Hdim*Sdim*DKdim];   // tf32-rounded
__device__ float g_V[Bdim*Hdim*Sdim*DKdim];   // tf32-rounded
__device__ float g_ctx[Bdim*Sdim*Ddim];       // [b,s,d] tf32-rounded
__device__ float g_xr[Mtot*Ddim];             // tf32-rounded encoder input
__device__ float g_wr[4*Ddim*Ddim];           // tf32-rounded Wq,Wk,Wv,Wo

// ---------------------------------------------------------------------------
__device__ __forceinline__ uint32_t f2tf32(float f) {
    uint32_t u;
    asm("cvt.rna.tf32.f32 %0, %1;" : "=r"(u) : "f"(f));
    return u;
}

__device__ __forceinline__ void mma_tf32(float c[4], const uint32_t a[4], const uint32_t b[2]) {
    asm volatile(
        "mma.sync.aligned.m16n8k8.row.col.f32.tf32.tf32.f32 "
        "{%0,%1,%2,%3},{%4,%5,%6,%7},{%8,%9},{%0,%1,%2,%3};"
        : "+f"(c[0]), "+f"(c[1]), "+f"(c[2]), "+f"(c[3])
        : "r"(a[0]), "r"(a[1]), "r"(a[2]), "r"(a[3]), "r"(b[0]), "r"(b[1]));
}

__device__ __forceinline__ void cp16(uint32_t dst, const void* src) {
    asm volatile("cp.async.cg.shared.global [%0], [%1], 16;" :: "r"(dst), "l"(src));
}

// ---------------------------------------------------------------------------
// Elementwise tf32 rounding pass (float4 granularity)
// ---------------------------------------------------------------------------
__global__ void round_tf32_kernel(const float* __restrict__ in,
                                  float* __restrict__ out, int n4)
{
    int i = blockIdx.x * 256 + threadIdx.x;
    if (i < n4) {
        float4 v = ((const float4*)in)[i];
        v.x = __uint_as_float(f2tf32(v.x));
        v.y = __uint_as_float(f2tf32(v.y));
        v.z = __uint_as_float(f2tf32(v.z));
        v.w = __uint_as_float(f2tf32(v.w));
        ((float4*)out)[i] = v;
    }
}

// ---------------------------------------------------------------------------
// TF32 tensor-core GEMM-NT on pre-rounded inputs (unchanged):
// C[m,n] = sum_k A[m,k]*W[n,k] + bias[n]
// ---------------------------------------------------------------------------
#define GP 36
#define GBUF (128*GP)

template<bool SCATTER>
__global__ void __launch_bounds__(256, 2)
gemm_tc(const float* __restrict__ A, const float* __restrict__ W,
        const float* __restrict__ bias, float* __restrict__ Cout)
{
    extern __shared__ float sm[];
    float* As = sm;
    float* Bs = sm + 2*GBUF;

    const int tid  = threadIdx.x;
    const int lane = tid & 31, warp = tid >> 5;
    const int wm   = warp >> 2, wn = warp & 3;
    const int m0   = blockIdx.y * 128, n0 = blockIdx.x * 128;

    float c[4][4][4];
#pragma unroll
    for (int i = 0; i < 4; i++)
#pragma unroll
        for (int j = 0; j < 4; j++)
#pragma unroll
            for (int t = 0; t < 4; t++) c[i][j][t] = 0.f;

    const int lr = tid >> 3;
    const int lc = (tid & 7) * 4;

#define GEMM_PREFETCH(kt, bufsel) do {                                          \
        const float* Ag_ = A + (size_t)m0 * 1024 + (kt) * 32;                   \
        const float* Wg_ = W + (size_t)n0 * 1024 + (kt) * 32;                   \
        uint32_t asb_ = (uint32_t)__cvta_generic_to_shared(As + (bufsel)*GBUF); \
        uint32_t bsb_ = (uint32_t)__cvta_generic_to_shared(Bs + (bufsel)*GBUF); \
        _Pragma("unroll")                                                       \
        for (int p_ = 0; p_ < 4; p_++) {                                        \
            int row_ = lr + p_ * 32;                                            \
            cp16(asb_ + (row_*GP + lc)*4, Ag_ + (size_t)row_*1024 + lc);        \
            cp16(bsb_ + (row_*GP + lc)*4, Wg_ + (size_t)row_*1024 + lc);        \
        }                                                                       \
        asm volatile("cp.async.commit_group;");                                 \
    } while (0)

    GEMM_PREFETCH(0, 0);

    for (int kt = 0; kt < 32; kt++) {
        if (kt + 1 < 32) {
            GEMM_PREFETCH(kt + 1, (kt + 1) & 1);
            asm volatile("cp.async.wait_group 1;");
        } else {
            asm volatile("cp.async.wait_group 0;");
        }
        __syncthreads();

        const float* Ab = As + (kt & 1) * GBUF + (wm * 64) * GP;
        const float* Bb = Bs + (kt & 1) * GBUF + (wn * 32) * GP;

#pragma unroll
        for (int ks = 0; ks < 4; ks++) {
            uint32_t a[4][4], b[4][2];
#pragma unroll
            for (int i = 0; i < 4; i++) {
                const float* ap = Ab + (i*16 + (lane >> 2)) * GP + ks*8 + (lane & 3);
                a[i][0] = __float_as_uint(ap[0]);
                a[i][1] = __float_as_uint(ap[8*GP]);
                a[i][2] = __float_as_uint(ap[4]);
                a[i][3] = __float_as_uint(ap[8*GP + 4]);
            }
#pragma unroll
            for (int j = 0; j < 4; j++) {
                const float* bp = Bb + (j*8 + (lane >> 2)) * GP + ks*8 + (lane & 3);
                b[j][0] = __float_as_uint(bp[0]);
                b[j][1] = __float_as_uint(bp[4]);
            }
#pragma unroll
            for (int i = 0; i < 4; i++)
#pragma unroll
                for (int j = 0; j < 4; j++)
                    mma_tf32(c[i][j], a[i], b[j]);
        }
        __syncthreads();
    }

#pragma unroll
    for (int i = 0; i < 4; i++) {
        const int r0 = m0 + wm*64 + i*16 + (lane >> 2);
#pragma unroll
        for (int j = 0; j < 4; j++) {
            const int n = n0 + wn*32 + j*8 + 2*(lane & 3);
            const float2 bb = *(const float2*)(bias + n);
            if (SCATTER) {
                float2 v0, v1;
                v0.x = __uint_as_float(f2tf32(c[i][j][0] + bb.x));
                v0.y = __uint_as_float(f2tf32(c[i][j][1] + bb.y));
                v1.x = __uint_as_float(f2tf32(c[i][j][2] + bb.x));
                v1.y = __uint_as_float(f2tf32(c[i][j][3] + bb.y));
                const int h_  = n >> 6, dk_ = n & 63;
                const int b_  = r0 >> 11, s_ = r0 & 2047;
                float* base = Cout + (((size_t)(b_*Hdim + h_) * Sdim + s_) * DKdim + dk_);
                *(float2*)base = v0;
                *(float2*)(base + 8 * DKdim) = v1;
            } else {
                float2 v0 = make_float2(c[i][j][0] + bb.x, c[i][j][1] + bb.y);
                float2 v1 = make_float2(c[i][j][2] + bb.x, c[i][j][3] + bb.y);
                *(float2*)(Cout + (size_t)r0 * 1024 + n) = v0;
                *(float2*)(Cout + (size_t)(r0 + 8) * 1024 + n) = v1;
            }
        }
    }
}

// ---------------------------------------------------------------------------
// Flash attention, tf32 MMA. Warp = 32 q-rows x 64 cols (two A-tiles share
// every B-fragment). CTA = (b,h) x 128 q rows, 128 threads (4 warps).
// P pitch fixed: 68 (P spans 64 columns; 36 was OOB -> round-5 crash).
// ---------------------------------------------------------------------------
#define QP 68   // pitch Qs/Ks: 68%32==4 -> conflict-free
#define VP 72   // pitch Vs:    72%32==8 -> conflict-free
#define PP 68   // pitch Ps:    >=64 cols, 68%32==4 -> conflict-free

__global__ void __launch_bounds__(128, 2)
attn_tc(const float* __restrict__ Q, const float* __restrict__ Kg,
        const float* __restrict__ Vg, float* __restrict__ ctx)
{
    extern __shared__ float sm[];
    float* Qs = sm;                       // [128][QP]  (q row, dk) pre-scaled
    float* Ks = Qs + 128*QP;              // [64][QP]   (kpos, dk)
    float* Vs = Ks + 64*QP;               // [64][VP]   (kpos, dk)
    float* Ps = Vs + 64*VP;               // [128][PP]  (q row, kpos)

    const int tid  = threadIdx.x;
    const int lane = tid & 31, warp = tid >> 5;
    const int bh = blockIdx.y;            // b*16+h
    const int b  = bh >> 4, h = bh & 15;
    const int q0 = blockIdx.x * 128;

    const float* Qp = Q  + ((size_t)bh * Sdim + q0) * DKdim;
    const float* Kp = Kg + (size_t)bh * Sdim * DKdim;
    const float* Vp = Vg + (size_t)bh * Sdim * DKdim;

    // Load Q tile, scale by 1/sqrt(dk)=0.125 (exact power of 2: stays tf32)
    for (int idx = tid; idx < 128*16; idx += 128) {
        const int row = idx >> 4, c4 = (idx & 15) << 2;
        float4 v = *(const float4*)(Qp + row * DKdim + c4);
        v.x *= 0.125f; v.y *= 0.125f; v.z *= 0.125f; v.w *= 0.125f;
        *(float4*)&Qs[row * QP + c4] = v;
    }

    float o[2][8][4];
#pragma unroll
    for (int i = 0; i < 2; i++)
#pragma unroll
        for (int j = 0; j < 8; j++)
#pragma unroll
            for (int t = 0; t < 4; t++) o[i][j][t] = 0.f;
    float mrow[2][2] = {{-1e30f, -1e30f}, {-1e30f, -1e30f}};
    float lsum[2][2] = {{0.f, 0.f}, {0.f, 0.f}};

    const int rA = warp*32 + (lane >> 2);    // base q-row (A-tile i adds i*16)
    const int cL = lane & 3;
    const int nL = lane >> 2;

    for (int kt = 0; kt < Sdim/64; kt++) {
        __syncthreads();   // previous iter done reading Ks/Vs (and Q load on kt==0)
        const float* Kt = Kp + kt * 64 * DKdim;
        const float* Vt = Vp + kt * 64 * DKdim;
        for (int idx = tid; idx < 64*16; idx += 128) {
            const int row = idx >> 4, c4 = (idx & 15) << 2;
            *(float4*)&Ks[row * QP + c4] = *(const float4*)(Kt + row * DKdim + c4);
            *(float4*)&Vs[row * VP + c4] = *(const float4*)(Vt + row * DKdim + c4);
        }
        __syncthreads();

        // ---- S = Q K^T : 32 rows (2 A-tiles) x 64 cols per warp ----
        float s[2][8][4];
#pragma unroll
        for (int i = 0; i < 2; i++)
#pragma unroll
            for (int j = 0; j < 8; j++)
#pragma unroll
                for (int t = 0; t < 4; t++) s[i][j][t] = 0.f;

#pragma unroll
        for (int ks = 0; ks < 8; ks++) {
            uint32_t a[2][4];
#pragma unroll
            for (int i = 0; i < 2; i++) {
                const float* qp = Qs + (rA + i*16) * QP + ks*8 + cL;
                a[i][0] = __float_as_uint(qp[0]);
                a[i][1] = __float_as_uint(qp[8*QP]);
                a[i][2] = __float_as_uint(qp[4]);
                a[i][3] = __float_as_uint(qp[8*QP + 4]);
            }
#pragma unroll
            for (int j = 0; j < 8; j++) {
                const float* kp = Ks + (j*8 + nL) * QP + ks*8 + cL;
                uint32_t bfr[2] = { __float_as_uint(kp[0]), __float_as_uint(kp[4]) };
                mma_tf32(s[0][j], a[0], bfr);
                mma_tf32(s[1][j], a[1], bfr);
            }
        }

        // ---- online softmax: 4 row-groups (i, hh) per thread ----
#pragma unroll
        for (int i = 0; i < 2; i++) {
#pragma unroll
            for (int hh = 0; hh < 2; hh++) {
                float tm = -1e30f;
#pragma unroll
                for (int j = 0; j < 8; j++)
                    tm = fmaxf(tm, fmaxf(s[i][j][hh*2], s[i][j][hh*2+1]));
                tm = fmaxf(tm, __shfl_xor_sync(0xffffffffu, tm, 1));
                tm = fmaxf(tm, __shfl_xor_sync(0xffffffffu, tm, 2));
                const float mnew  = fmaxf(mrow[i][hh], tm);
                const float alpha = __expf(mrow[i][hh] - mnew);
                mrow[i][hh] = mnew;
                float rs = 0.f;
#pragma unroll
                for (int j = 0; j < 8; j++) {
                    const float p0 = __expf(s[i][j][hh*2]   - mnew);
                    const float p1 = __expf(s[i][j][hh*2+1] - mnew);
                    s[i][j][hh*2] = p0; s[i][j][hh*2+1] = p1;
                    rs += p0 + p1;
                }
                rs += __shfl_xor_sync(0xffffffffu, rs, 1);
                rs += __shfl_xor_sync(0xffffffffu, rs, 2);
                lsum[i][hh] = lsum[i][hh] * alpha + rs;
#pragma unroll
                for (int j = 0; j < 8; j++) {
                    o[i][j][hh*2]   *= alpha;
                    o[i][j][hh*2+1] *= alpha;
                }
            }
        }

        // ---- P -> smem, tf32-rounded at store (warp-local rows) ----
#pragma unroll
        for (int i = 0; i < 2; i++) {
#pragma unroll
            for (int j = 0; j < 8; j++) {
#pragma unroll
                for (int hh = 0; hh < 2; hh++) {
                    float2 pv;
                    pv.x = __uint_as_float(f2tf32(s[i][j][hh*2]));
                    pv.y = __uint_as_float(f2tf32(s[i][j][hh*2+1]));
                    *(float2*)&Ps[(rA + i*16 + hh*8) * PP + j*8 + 2*cL] = pv;
                }
            }
        }
        __syncwarp();

        // ---- O += P V : same B-fragment reuse across both A-tiles ----
#pragma unroll
        for (int ks = 0; ks < 8; ks++) {
            uint32_t a[2][4];
#pragma unroll
            for (int i = 0; i < 2; i++) {
                const float* pp = Ps + (rA + i*16) * PP + ks*8 + cL;
                a[i][0] = __float_as_uint(pp[0]);
                a[i][1] = __float_as_uint(pp[8*PP]);
                a[i][2] = __float_as_uint(pp[4]);
                a[i][3] = __float_as_uint(pp[8*PP + 4]);
            }
#pragma unroll
            for (int j = 0; j < 8; j++) {
                const float* vp = Vs + (ks*8 + cL) * VP + j*8 + nL;
                uint32_t bfr[2] = { __float_as_uint(vp[0]), __float_as_uint(vp[4*VP]) };
                mma_tf32(o[0][j], a[0], bfr);
                mma_tf32(o[1][j], a[1], bfr);
            }
        }
    }

    // ---- epilogue: normalize, round to tf32, write ctx [b,s,d] ----
#pragma unroll
    for (int i = 0; i < 2; i++) {
#pragma unroll
        for (int hh = 0; hh < 2; hh++) {
            const float inv = 1.f / lsum[i][hh];
            const int srow = q0 + rA + i*16 + hh*8;
            float* base = ctx + ((size_t)b * Sdim + srow) * Ddim + h * DKdim;
#pragma unroll
            for (int j = 0; j < 8; j++) {
                float2 ov;
                ov.x = __uint_as_float(f2tf32(o[i][j][hh*2]   * inv));
                ov.y = __uint_as_float(f2tf32(o[i][j][hh*2+1] * inv));
                *(float2*)(base + j*8 + 2*cL) = ov;
            }
        }
    }
}

// ---------------------------------------------------------------------------
extern "C" void kernel_launch(void* const* d_in, const int* in_sizes, int n_in,
                              void* d_out, int out_size)
{
    (void)in_sizes; (void)n_in; (void)out_size;
    const float* x  = (const float*)d_in[0];
    // d_in[1] = attention_mask (unused by reference forward)
    const float* Wq = (const float*)d_in[2];
    const float* bq = (const float*)d_in[3];
    const float* Wk = (const float*)d_in[4];
    const float* bk = (const float*)d_in[5];
    const float* Wv = (const float*)d_in[6];
    const float* bv = (const float*)d_in[7];
    const float* Wo = (const float*)d_in[8];
    const float* bo = (const float*)d_in[9];
    float* out = (float*)d_out;

    float *Qb, *Kb, *Vb, *Cb, *Xr, *Wr;
    cudaGetSymbolAddress((void**)&Qb, g_Q);
    cudaGetSymbolAddress((void**)&Kb, g_K);
    cudaGetSymbolAddress((void**)&Vb, g_V);
    cudaGetSymbolAddress((void**)&Cb, g_ctx);
    cudaGetSymbolAddress((void**)&Xr, g_xr);
    cudaGetSymbolAddress((void**)&Wr, g_wr);

    const int GEMM_SMEM = 4 * GBUF * (int)sizeof(float);                           // 73728
    const int ATTN_SMEM = (128*QP + 64*QP + 64*VP + 128*PP) * (int)sizeof(float);  // 105472

    cudaFuncSetAttribute(gemm_tc<true>,
                         cudaFuncAttributeMaxDynamicSharedMemorySize, GEMM_SMEM);
    cudaFuncSetAttribute(gemm_tc<false>,
                         cudaFuncAttributeMaxDynamicSharedMemorySize, GEMM_SMEM);
    cudaFuncSetAttribute(attn_tc,
                         cudaFuncAttributeMaxDynamicSharedMemorySize, ATTN_SMEM);

    // tf32 pre-rounding passes (round once per element at the producer)
    round_tf32_kernel<<<(Mtot*Ddim/4 + 255)/256, 256>>>(x, Xr, Mtot*Ddim/4);
    round_tf32_kernel<<<(Ddim*Ddim/4 + 255)/256, 256>>>(Wq, Wr + 0*Ddim*Ddim, Ddim*Ddim/4);
    round_tf32_kernel<<<(Ddim*Ddim/4 + 255)/256, 256>>>(Wk, Wr + 1*Ddim*Ddim, Ddim*Ddim/4);
    round_tf32_kernel<<<(Ddim*Ddim/4 + 255)/256, 256>>>(Wv, Wr + 2*Ddim*Ddim, Ddim*Ddim/4);
    round_tf32_kernel<<<(Ddim*Ddim/4 + 255)/256, 256>>>(Wo, Wr + 3*Ddim*Ddim, Ddim*Ddim/4);

    const dim3 gg(Ddim / 128, Mtot / 128);   // (8, 64)
    gemm_tc<true><<<gg, 256, GEMM_SMEM>>>(Xr, Wr + 0*Ddim*Ddim, bq, Qb);
    gemm_tc<true><<<gg, 256, GEMM_SMEM>>>(Xr, Wr + 1*Ddim*Ddim, bk, Kb);
    gemm_tc<true><<<gg, 256, GEMM_SMEM>>>(Xr, Wr + 2*Ddim*Ddim, bv, Vb);

    attn_tc<<<dim3(Sdim / 128, Bdim * Hdim), 128, ATTN_SMEM>>>(Qb, Kb, Vb, Cb);

    gemm_tc<false><<<gg, 256, GEMM_SMEM>>>(Cb, Wr + 3*Ddim*Ddim, bo, out);
}

// round 8
// speedup vs baseline: 3.3317x; 1.0109x over previous
#include <cuda_runtime.h>
#include <math.h>
#include <stdint.h>

#define Bdim 4
#define Sdim 2048
#define Ddim 1024
#define Hdim 16
#define DKdim 64
#define Mtot (Bdim*Sdim)   // 8192

// Scratch (device globals: sanctioned no-alloc workaround)
__device__ float g_Q[Bdim*Hdim*Sdim*DKdim];   // [b,h,s,dk] tf32-rounded
__device__ float g_K[Bdim*Hdim*Sdim*DKdim];   // tf32-rounded
__device__ float g_V[Bdim*Hdim*Sdim*DKdim];   // tf32-rounded
__device__ float g_ctx[Bdim*Sdim*Ddim];       // [b,s,d] tf32-rounded
__device__ float g_xr[Mtot*Ddim];             // tf32-rounded encoder input
__device__ float g_wr[4*Ddim*Ddim];           // tf32-rounded Wq,Wk,Wv,Wo

// ---------------------------------------------------------------------------
__device__ __forceinline__ uint32_t f2tf32(float f) {
    uint32_t u;
    asm("cvt.rna.tf32.f32 %0, %1;" : "=r"(u) : "f"(f));
    return u;
}

__device__ __forceinline__ void mma_tf32(float c[4], const uint32_t a[4], const uint32_t b[2]) {
    asm volatile(
        "mma.sync.aligned.m16n8k8.row.col.f32.tf32.tf32.f32 "
        "{%0,%1,%2,%3},{%4,%5,%6,%7},{%8,%9},{%0,%1,%2,%3};"
        : "+f"(c[0]), "+f"(c[1]), "+f"(c[2]), "+f"(c[3])
        : "r"(a[0]), "r"(a[1]), "r"(a[2]), "r"(a[3]), "r"(b[0]), "r"(b[1]));
}

__device__ __forceinline__ void cp16(uint32_t dst, const void* src) {
    asm volatile("cp.async.cg.shared.global [%0], [%1], 16;" :: "r"(dst), "l"(src));
}

// ---------------------------------------------------------------------------
// Elementwise tf32 rounding pass (float4 granularity)
// ---------------------------------------------------------------------------
__global__ void round_tf32_kernel(const float* __restrict__ in,
                                  float* __restrict__ out, int n4)
{
    int i = blockIdx.x * 256 + threadIdx.x;
    if (i < n4) {
        float4 v = ((const float4*)in)[i];
        v.x = __uint_as_float(f2tf32(v.x));
        v.y = __uint_as_float(f2tf32(v.y));
        v.z = __uint_as_float(f2tf32(v.z));
        v.w = __uint_as_float(f2tf32(v.w));
        ((float4*)out)[i] = v;
    }
}

// ---------------------------------------------------------------------------
// TF32 tensor-core GEMM-NT on pre-rounded inputs (round-6 proven version):
// C[m,n] = sum_k A[m,k]*W[n,k] + bias[n]
// ---------------------------------------------------------------------------
#define GP 36
#define GBUF (128*GP)

template<bool SCATTER>
__global__ void __launch_bounds__(256, 2)
gemm_tc(const float* __restrict__ A, const float* __restrict__ W,
        const float* __restrict__ bias, float* __restrict__ Cout)
{
    extern __shared__ float sm[];
    float* As = sm;
    float* Bs = sm + 2*GBUF;

    const int tid  = threadIdx.x;
    const int lane = tid & 31, warp = tid >> 5;
    const int wm   = warp >> 2, wn = warp & 3;
    const int m0   = blockIdx.y * 128, n0 = blockIdx.x * 128;

    float c[4][4][4];
#pragma unroll
    for (int i = 0; i < 4; i++)
#pragma unroll
        for (int j = 0; j < 4; j++)
#pragma unroll
            for (int t = 0; t < 4; t++) c[i][j][t] = 0.f;

    const int lr = tid >> 3;
    const int lc = (tid & 7) * 4;

#define GEMM_PREFETCH(kt, bufsel) do {                                          \
        const float* Ag_ = A + (size_t)m0 * 1024 + (kt) * 32;                   \
        const float* Wg_ = W + (size_t)n0 * 1024 + (kt) * 32;                   \
        uint32_t asb_ = (uint32_t)__cvta_generic_to_shared(As + (bufsel)*GBUF); \
        uint32_t bsb_ = (uint32_t)__cvta_generic_to_shared(Bs + (bufsel)*GBUF); \
        _Pragma("unroll")                                                       \
        for (int p_ = 0; p_ < 4; p_++) {                                        \
            int row_ = lr + p_ * 32;                                            \
            cp16(asb_ + (row_*GP + lc)*4, Ag_ + (size_t)row_*1024 + lc);        \
            cp16(bsb_ + (row_*GP + lc)*4, Wg_ + (size_t)row_*1024 + lc);        \
        }                                                                       \
        asm volatile("cp.async.commit_group;");                                 \
    } while (0)

    GEMM_PREFETCH(0, 0);

    for (int kt = 0; kt < 32; kt++) {
        if (kt + 1 < 32) {
            GEMM_PREFETCH(kt + 1, (kt + 1) & 1);
            asm volatile("cp.async.wait_group 1;");
        } else {
            asm volatile("cp.async.wait_group 0;");
        }
        __syncthreads();

        const float* Ab = As + (kt & 1) * GBUF + (wm * 64) * GP;
        const float* Bb = Bs + (kt & 1) * GBUF + (wn * 32) * GP;

#pragma unroll
        for (int ks = 0; ks < 4; ks++) {
            uint32_t a[4][4], b[4][2];
#pragma unroll
            for (int i = 0; i < 4; i++) {
                const float* ap = Ab + (i*16 + (lane >> 2)) * GP + ks*8 + (lane & 3);
                a[i][0] = __float_as_uint(ap[0]);
                a[i][1] = __float_as_uint(ap[8*GP]);
                a[i][2] = __float_as_uint(ap[4]);
                a[i][3] = __float_as_uint(ap[8*GP + 4]);
            }
#pragma unroll
            for (int j = 0; j < 4; j++) {
                const float* bp = Bb + (j*8 + (lane >> 2)) * GP + ks*8 + (lane & 3);
                b[j][0] = __float_as_uint(bp[0]);
                b[j][1] = __float_as_uint(bp[4]);
            }
#pragma unroll
            for (int i = 0; i < 4; i++)
#pragma unroll
                for (int j = 0; j < 4; j++)
                    mma_tf32(c[i][j], a[i], b[j]);
        }
        __syncthreads();
    }

#pragma unroll
    for (int i = 0; i < 4; i++) {
        const int r0 = m0 + wm*64 + i*16 + (lane >> 2);
#pragma unroll
        for (int j = 0; j < 4; j++) {
            const int n = n0 + wn*32 + j*8 + 2*(lane & 3);
            const float2 bb = *(const float2*)(bias + n);
            if (SCATTER) {
                float2 v0, v1;
                v0.x = __uint_as_float(f2tf32(c[i][j][0] + bb.x));
                v0.y = __uint_as_float(f2tf32(c[i][j][1] + bb.y));
                v1.x = __uint_as_float(f2tf32(c[i][j][2] + bb.x));
                v1.y = __uint_as_float(f2tf32(c[i][j][3] + bb.y));
                const int h_  = n >> 6, dk_ = n & 63;
                const int b_  = r0 >> 11, s_ = r0 & 2047;
                float* base = Cout + (((size_t)(b_*Hdim + h_) * Sdim + s_) * DKdim + dk_);
                *(float2*)base = v0;
                *(float2*)(base + 8 * DKdim) = v1;
            } else {
                float2 v0 = make_float2(c[i][j][0] + bb.x, c[i][j][1] + bb.y);
                float2 v1 = make_float2(c[i][j][2] + bb.x, c[i][j][3] + bb.y);
                *(float2*)(Cout + (size_t)r0 * 1024 + n) = v0;
                *(float2*)(Cout + (size_t)(r0 + 8) * 1024 + n) = v1;
            }
        }
    }
}

// ---------------------------------------------------------------------------
// Flash attention, tf32 MMA. Round 8:
//  - CTA = (b,h) x 256 q rows, 256 threads (8 warps x 32 q-rows each).
//    K/V tile loads amortized over 2x more q rows.
//  - K/V 64-row tiles, cp.async 2-stage double buffer (global latency hidden).
// Per-warp tiling/math identical to round 6 -> rel_err must stay bit-identical.
// ---------------------------------------------------------------------------
#define QROWS 256
#define QP 68   // pitch Qs/Ks: 68%32==4 -> conflict-free
#define VP 72   // pitch Vs:    72%32==8 -> conflict-free
#define PP 68   // pitch Ps:    spans 64 cols, conflict-free

__global__ void __launch_bounds__(256, 1)
attn_tc(const float* __restrict__ Q, const float* __restrict__ Kg,
        const float* __restrict__ Vg, float* __restrict__ ctx)
{
    extern __shared__ float sm[];
    float* Qs = sm;                         // [256][QP]   (q row, dk) pre-scaled
    float* Ks = Qs + QROWS*QP;              // [2][64][QP] (kpos, dk)
    float* Vs = Ks + 2*64*QP;               // [2][64][VP] (kpos, dk)
    float* Ps = Vs + 2*64*VP;               // [256][PP]   (q row, kpos)

    const int tid  = threadIdx.x;
    const int lane = tid & 31, warp = tid >> 5;
    const int bh = blockIdx.y;              // b*16+h
    const int b  = bh >> 4, h = bh & 15;
    const int q0 = blockIdx.x * QROWS;

    const float* Qp = Q  + ((size_t)bh * Sdim + q0) * DKdim;
    const float* Kp = Kg + (size_t)bh * Sdim * DKdim;
    const float* Vp = Vg + (size_t)bh * Sdim * DKdim;

    const uint32_t ks_base = (uint32_t)__cvta_generic_to_shared(Ks);
    const uint32_t vs_base = (uint32_t)__cvta_generic_to_shared(Vs);

    // Prefetch one 64-row K/V tile into buffer bs (cp.async, committed as a group)
#define ATTN_PRE(kt2, bs) do {                                              \
        const float* Kt_ = Kp + (size_t)(kt2) * 64 * DKdim;                 \
        const float* Vt_ = Vp + (size_t)(kt2) * 64 * DKdim;                 \
        const uint32_t kb_ = ks_base + (bs) * (64*QP*4);                    \
        const uint32_t vb_ = vs_base + (bs) * (64*VP*4);                    \
        _Pragma("unroll")                                                   \
        for (int p_ = 0; p_ < 4; p_++) {                                    \
            const int idx_ = tid + 256 * p_;                                \
            const int row_ = idx_ >> 4, c4_ = (idx_ & 15) << 2;             \
            cp16(kb_ + (row_*QP + c4_)*4, Kt_ + row_*DKdim + c4_);          \
            cp16(vb_ + (row_*VP + c4_)*4, Vt_ + row_*DKdim + c4_);          \
        }                                                                   \
        asm volatile("cp.async.commit_group;");                             \
    } while (0)

    ATTN_PRE(0, 0);

    // Load Q tile (plain LDG->STS), scale by 1/sqrt(dk)=0.125 (exact pow2)
    for (int idx = tid; idx < QROWS*16; idx += 256) {
        const int row = idx >> 4, c4 = (idx & 15) << 2;
        float4 v = *(const float4*)(Qp + row * DKdim + c4);
        v.x *= 0.125f; v.y *= 0.125f; v.z *= 0.125f; v.w *= 0.125f;
        *(float4*)&Qs[row * QP + c4] = v;
    }

    float o[2][8][4];
#pragma unroll
    for (int i = 0; i < 2; i++)
#pragma unroll
        for (int j = 0; j < 8; j++)
#pragma unroll
            for (int t = 0; t < 4; t++) o[i][j][t] = 0.f;
    float mrow[2][2] = {{-1e30f, -1e30f}, {-1e30f, -1e30f}};
    float lsum[2][2] = {{0.f, 0.f}, {0.f, 0.f}};

    const int rA = warp*32 + (lane >> 2);    // base q-row (A-tile i adds i*16)
    const int cL = lane & 3;
    const int nL = lane >> 2;

    for (int kt = 0; kt < Sdim/64; kt++) {
        const int buf = kt & 1;
        // prefetch next tile into buf^1 (its previous readers finished at the
        // trailing __syncthreads of iteration kt-1)
        if (kt + 1 < Sdim/64) {
            ATTN_PRE(kt + 1, buf ^ 1);
            asm volatile("cp.async.wait_group 1;");   // tile kt has landed
        } else {
            asm volatile("cp.async.wait_group 0;");
        }
        __syncthreads();   // tile kt (and Q on kt==0) visible to all warps

        const float* Kb = Ks + buf * (64*QP);
        const float* Vb = Vs + buf * (64*VP);

        // ---- S = Q K^T : 32 rows (2 A-tiles) x 64 cols per warp ----
        float s[2][8][4];
#pragma unroll
        for (int i = 0; i < 2; i++)
#pragma unroll
            for (int j = 0; j < 8; j++)
#pragma unroll
                for (int t = 0; t < 4; t++) s[i][j][t] = 0.f;

#pragma unroll
        for (int ks = 0; ks < 8; ks++) {
            uint32_t a[2][4];
#pragma unroll
            for (int i = 0; i < 2; i++) {
                const float* qp = Qs + (rA + i*16) * QP + ks*8 + cL;
                a[i][0] = __float_as_uint(qp[0]);
                a[i][1] = __float_as_uint(qp[8*QP]);
                a[i][2] = __float_as_uint(qp[4]);
                a[i][3] = __float_as_uint(qp[8*QP + 4]);
            }
#pragma unroll
            for (int j = 0; j < 8; j++) {
                const float* kp = Kb + (j*8 + nL) * QP + ks*8 + cL;
                uint32_t bfr[2] = { __float_as_uint(kp[0]), __float_as_uint(kp[4]) };
                mma_tf32(s[0][j], a[0], bfr);
                mma_tf32(s[1][j], a[1], bfr);
            }
        }

        // ---- online softmax: 4 row-groups (i, hh) per thread ----
#pragma unroll
        for (int i = 0; i < 2; i++) {
#pragma unroll
            for (int hh = 0; hh < 2; hh++) {
                float tm = -1e30f;
#pragma unroll
                for (int j = 0; j < 8; j++)
                    tm = fmaxf(tm, fmaxf(s[i][j][hh*2], s[i][j][hh*2+1]));
                tm = fmaxf(tm, __shfl_xor_sync(0xffffffffu, tm, 1));
                tm = fmaxf(tm, __shfl_xor_sync(0xffffffffu, tm, 2));
                const float mnew  = fmaxf(mrow[i][hh], tm);
                const float alpha = __expf(mrow[i][hh] - mnew);
                mrow[i][hh] = mnew;
                float rs = 0.f;
#pragma unroll
                for (int j = 0; j < 8; j++) {
                    const float p0 = __expf(s[i][j][hh*2]   - mnew);
                    const float p1 = __expf(s[i][j][hh*2+1] - mnew);
                    s[i][j][hh*2] = p0; s[i][j][hh*2+1] = p1;
                    rs += p0 + p1;
                }
                rs += __shfl_xor_sync(0xffffffffu, rs, 1);
                rs += __shfl_xor_sync(0xffffffffu, rs, 2);
                lsum[i][hh] = lsum[i][hh] * alpha + rs;
#pragma unroll
                for (int j = 0; j < 8; j++) {
                    o[i][j][hh*2]   *= alpha;
                    o[i][j][hh*2+1] *= alpha;
                }
            }
        }

        // ---- P -> smem, tf32-rounded at store (warp-local rows) ----
#pragma unroll
        for (int i = 0; i < 2; i++) {
#pragma unroll
            for (int j = 0; j < 8; j++) {
#pragma unroll
                for (int hh = 0; hh < 2; hh++) {
                    float2 pv;
                    pv.x = __uint_as_float(f2tf32(s[i][j][hh*2]));
                    pv.y = __uint_as_float(f2tf32(s[i][j][hh*2+1]));
                    *(float2*)&Ps[(rA + i*16 + hh*8) * PP + j*8 + 2*cL] = pv;
                }
            }
        }
        __syncwarp();

        // ---- O += P V : B-fragment reuse across both A-tiles ----
#pragma unroll
        for (int ks = 0; ks < 8; ks++) {
            uint32_t a[2][4];
#pragma unroll
            for (int i = 0; i < 2; i++) {
                const float* pp = Ps + (rA + i*16) * PP + ks*8 + cL;
                a[i][0] = __float_as_uint(pp[0]);
                a[i][1] = __float_as_uint(pp[8*PP]);
                a[i][2] = __float_as_uint(pp[4]);
                a[i][3] = __float_as_uint(pp[8*PP + 4]);
            }
#pragma unroll
            for (int j = 0; j < 8; j++) {
                const float* vp = Vb + (ks*8 + cL) * VP + j*8 + nL;
                uint32_t bfr[2] = { __float_as_uint(vp[0]), __float_as_uint(vp[4*VP]) };
                mma_tf32(o[0][j], a[0], bfr);
                mma_tf32(o[1][j], a[1], bfr);
            }
        }

        __syncthreads();   // all warps done reading buf before next prefetch reuses it
    }

    // ---- epilogue: normalize, round to tf32, write ctx [b,s,d] ----
#pragma unroll
    for (int i = 0; i < 2; i++) {
#pragma unroll
        for (int hh = 0; hh < 2; hh++) {
            const float inv = 1.f / lsum[i][hh];
            const int srow = q0 + rA + i*16 + hh*8;
            float* base = ctx + ((size_t)b * Sdim + srow) * Ddim + h * DKdim;
#pragma unroll
            for (int j = 0; j < 8; j++) {
                float2 ov;
                ov.x = __uint_as_float(f2tf32(o[i][j][hh*2]   * inv));
                ov.y = __uint_as_float(f2tf32(o[i][j][hh*2+1] * inv));
                *(float2*)(base + j*8 + 2*cL) = ov;
            }
        }
    }
}

// ---------------------------------------------------------------------------
extern "C" void kernel_launch(void* const* d_in, const int* in_sizes, int n_in,
                              void* d_out, int out_size)
{
    (void)in_sizes; (void)n_in; (void)out_size;
    const float* x  = (const float*)d_in[0];
    // d_in[1] = attention_mask (unused by reference forward)
    const float* Wq = (const float*)d_in[2];
    const float* bq = (const float*)d_in[3];
    const float* Wk = (const float*)d_in[4];
    const float* bk = (const float*)d_in[5];
    const float* Wv = (const float*)d_in[6];
    const float* bv = (const float*)d_in[7];
    const float* Wo = (const float*)d_in[8];
    const float* bo = (const float*)d_in[9];
    float* out = (float*)d_out;

    float *Qb, *Kb, *Vb, *Cb, *Xr, *Wr;
    cudaGetSymbolAddress((void**)&Qb, g_Q);
    cudaGetSymbolAddress((void**)&Kb, g_K);
    cudaGetSymbolAddress((void**)&Vb, g_V);
    cudaGetSymbolAddress((void**)&Cb, g_ctx);
    cudaGetSymbolAddress((void**)&Xr, g_xr);
    cudaGetSymbolAddress((void**)&Wr, g_wr);

    const int GEMM_SMEM = 4 * GBUF * (int)sizeof(float);   // 73728
    const int ATTN_SMEM = (QROWS*QP + 2*64*QP + 2*64*VP + QROWS*PP) * (int)sizeof(float); // 210944

    cudaFuncSetAttribute(gemm_tc<true>,
                         cudaFuncAttributeMaxDynamicSharedMemorySize, GEMM_SMEM);
    cudaFuncSetAttribute(gemm_tc<false>,
                         cudaFuncAttributeMaxDynamicSharedMemorySize, GEMM_SMEM);
    cudaFuncSetAttribute(attn_tc,
                         cudaFuncAttributeMaxDynamicSharedMemorySize, ATTN_SMEM);

    // tf32 pre-rounding passes (round once per element at the producer)
    round_tf32_kernel<<<(Mtot*Ddim/4 + 255)/256, 256>>>(x, Xr, Mtot*Ddim/4);
    round_tf32_kernel<<<(Ddim*Ddim/4 + 255)/256, 256>>>(Wq, Wr + 0*Ddim*Ddim, Ddim*Ddim/4);
    round_tf32_kernel<<<(Ddim*Ddim/4 + 255)/256, 256>>>(Wk, Wr + 1*Ddim*Ddim, Ddim*Ddim/4);
    round_tf32_kernel<<<(Ddim*Ddim/4 + 255)/256, 256>>>(Wv, Wr + 2*Ddim*Ddim, Ddim*Ddim/4);
    round_tf32_kernel<<<(Ddim*Ddim/4 + 255)/256, 256>>>(Wo, Wr + 3*Ddim*Ddim, Ddim*Ddim/4);

    const dim3 gg(Ddim / 128, Mtot / 128);   // (8, 64)
    gemm_tc<true><<<gg, 256, GEMM_SMEM>>>(Xr, Wr + 0*Ddim*Ddim, bq, Qb);
    gemm_tc<true><<<gg, 256, GEMM_SMEM>>>(Xr, Wr + 1*Ddim*Ddim, bk, Kb);
    gemm_tc<true><<<gg, 256, GEMM_SMEM>>>(Xr, Wr + 2*Ddim*Ddim, bv, Vb);

    attn_tc<<<dim3(Sdim / QROWS, Bdim * Hdim), 256, ATTN_SMEM>>>(Qb, Kb, Vb, Cb);

    gemm_tc<false><<<gg, 256, GEMM_SMEM>>>(Cb, Wr + 3*Ddim*Ddim, bo, out);
}

// round 9
// speedup vs baseline: 5.9118x; 1.7744x over previous
#include <cuda_runtime.h>
#include <cuda_fp16.h>
#include <math.h>
#include <stdint.h>

#define Bdim 4
#define Sdim 2048
#define Ddim 1024
#define Hdim 16
#define DKdim 64
#define Mtot (Bdim*Sdim)   // 8192

// Scratch (device globals: sanctioned no-alloc workaround)
__device__ __half g_Q[Bdim*Hdim*Sdim*DKdim];   // [b,h,s,dk] fp16
__device__ __half g_K[Bdim*Hdim*Sdim*DKdim];
__device__ __half g_V[Bdim*Hdim*Sdim*DKdim];
__device__ __half g_ctx[Bdim*Sdim*Ddim];       // [b,s,d] fp16
__device__ __half g_xh[Mtot*Ddim];             // fp16 encoder input
__device__ __half g_wh[4*Ddim*Ddim];           // fp16 Wq,Wk,Wv,Wo

// ---------------------------------------------------------------------------
__device__ __forceinline__ void mma_f16(float c[4], const uint32_t a[4],
                                        uint32_t b0, uint32_t b1) {
    asm volatile(
        "mma.sync.aligned.m16n8k16.row.col.f32.f16.f16.f32 "
        "{%0,%1,%2,%3},{%4,%5,%6,%7},{%8,%9},{%0,%1,%2,%3};"
        : "+f"(c[0]), "+f"(c[1]), "+f"(c[2]), "+f"(c[3])
        : "r"(a[0]), "r"(a[1]), "r"(a[2]), "r"(a[3]), "r"(b0), "r"(b1));
}

__device__ __forceinline__ void ldsm_x4_t(uint32_t& r0, uint32_t& r1,
                                          uint32_t& r2, uint32_t& r3, uint32_t a) {
    asm volatile("ldmatrix.sync.aligned.m8n8.x4.trans.shared.b16 {%0,%1,%2,%3}, [%4];"
                 : "=r"(r0), "=r"(r1), "=r"(r2), "=r"(r3) : "r"(a));
}

__device__ __forceinline__ void cp16(uint32_t dst, const void* src) {
    asm volatile("cp.async.cg.shared.global [%0], [%1], 16;" :: "r"(dst), "l"(src));
}

__device__ __forceinline__ uint32_t h2u(__half2 h) { return *(uint32_t*)&h; }

// ---------------------------------------------------------------------------
// fp32 -> fp16 conversion pass (8 elements / thread)
// ---------------------------------------------------------------------------
__global__ void to_half_kernel(const float* __restrict__ in,
                               __half* __restrict__ out, int n8)
{
    int i = blockIdx.x * 256 + threadIdx.x;
    if (i < n8) {
        const float4 a = ((const float4*)in)[2*i];
        const float4 b = ((const float4*)in)[2*i+1];
        uint4 o;
        o.x = h2u(__floats2half2_rn(a.x, a.y));
        o.y = h2u(__floats2half2_rn(a.z, a.w));
        o.z = h2u(__floats2half2_rn(b.x, b.y));
        o.w = h2u(__floats2half2_rn(b.z, b.w));
        ((uint4*)out)[i] = o;
    }
}

// ---------------------------------------------------------------------------
// fp16 tensor-core GEMM-NT: C[m,n] = sum_k A[m,k]*W[n,k] + bias[n]
// BM=BN=128, BK=32 halfs, 256 thr, warp = 64x32, m16n8k16 MMA.
// SCATTER: write fp16 to [b,h,s,dk]; else fp32 [m,n].
// Smem unit: uint32 word = fp16x2. PWG=20 words/row -> frag loads conflict-free.
// ---------------------------------------------------------------------------
#define PWG 20
#define GBUF (128*PWG)    // words per operand buffer

template<bool SCATTER>
__global__ void __launch_bounds__(256, 2)
gemm_f16(const __half* __restrict__ A, const __half* __restrict__ W,
         const float* __restrict__ bias, void* __restrict__ Cout)
{
    extern __shared__ uint32_t smw[];
    uint32_t* Asw = smw;               // [2][128][PWG]
    uint32_t* Bsw = smw + 2*GBUF;      // [2][128][PWG]

    const int tid  = threadIdx.x;
    const int lane = tid & 31, warp = tid >> 5;
    const int wm   = warp >> 2, wn = warp & 3;
    const int m0   = blockIdx.y * 128, n0 = blockIdx.x * 128;
    const int cL   = lane & 3, nL = lane >> 2;

    float c[4][4][4];
#pragma unroll
    for (int i = 0; i < 4; i++)
#pragma unroll
        for (int j = 0; j < 4; j++)
#pragma unroll
            for (int t = 0; t < 4; t++) c[i][j][t] = 0.f;

    const uint32_t asb = (uint32_t)__cvta_generic_to_shared(Asw);
    const uint32_t bsb = (uint32_t)__cvta_generic_to_shared(Bsw);

#define GEMM_PRE(kt, bs) do {                                               \
        const __half* Ag_ = A + (size_t)m0 * 1024 + (kt) * 32;              \
        const __half* Wg_ = W + (size_t)n0 * 1024 + (kt) * 32;              \
        const uint32_t as_ = asb + (bs) * (GBUF*4);                         \
        const uint32_t bs_ = bsb + (bs) * (GBUF*4);                         \
        _Pragma("unroll")                                                   \
        for (int p_ = 0; p_ < 2; p_++) {                                    \
            const int idx_ = tid + 256 * p_;                                \
            const int row_ = idx_ >> 2, c_ = idx_ & 3;                      \
            cp16(as_ + (row_*PWG + c_*4)*4, Ag_ + (size_t)row_*1024 + c_*8);\
            cp16(bs_ + (row_*PWG + c_*4)*4, Wg_ + (size_t)row_*1024 + c_*8);\
        }                                                                   \
        asm volatile("cp.async.commit_group;");                             \
    } while (0)

    GEMM_PRE(0, 0);

    for (int kt = 0; kt < 32; kt++) {
        if (kt + 1 < 32) {
            GEMM_PRE(kt + 1, (kt + 1) & 1);
            asm volatile("cp.async.wait_group 1;");
        } else {
            asm volatile("cp.async.wait_group 0;");
        }
        __syncthreads();

        const uint32_t* Ab = Asw + (kt & 1) * GBUF + (wm * 64) * PWG;
        const uint32_t* Bb = Bsw + (kt & 1) * GBUF + (wn * 32) * PWG;

#pragma unroll
        for (int ks = 0; ks < 2; ks++) {
            uint32_t a[4][4], b[4][2];
#pragma unroll
            for (int i = 0; i < 4; i++) {
                const uint32_t* ap = Ab + (i*16 + nL) * PWG + ks*8 + cL;
                a[i][0] = ap[0];
                a[i][1] = ap[8*PWG];
                a[i][2] = ap[4];
                a[i][3] = ap[8*PWG + 4];
            }
#pragma unroll
            for (int j = 0; j < 4; j++) {
                const uint32_t* bp = Bb + (j*8 + nL) * PWG + ks*8 + cL;
                b[j][0] = bp[0];
                b[j][1] = bp[4];
            }
#pragma unroll
            for (int i = 0; i < 4; i++)
#pragma unroll
                for (int j = 0; j < 4; j++)
                    mma_f16(c[i][j], a[i], b[j][0], b[j][1]);
        }
        __syncthreads();
    }

    // epilogue
#pragma unroll
    for (int i = 0; i < 4; i++) {
        const int r0 = m0 + wm*64 + i*16 + nL;
#pragma unroll
        for (int j = 0; j < 4; j++) {
            const int n = n0 + wn*32 + j*8 + 2*cL;
            const float2 bb = *(const float2*)(bias + n);
            if (SCATTER) {
                __half2 v0 = __floats2half2_rn(c[i][j][0] + bb.x, c[i][j][1] + bb.y);
                __half2 v1 = __floats2half2_rn(c[i][j][2] + bb.x, c[i][j][3] + bb.y);
                const int h_  = n >> 6, dk_ = n & 63;
                const int b_  = r0 >> 11, s_ = r0 & 2047;
                __half* base = (__half*)Cout + (((size_t)(b_*Hdim + h_) * Sdim + s_) * DKdim + dk_);
                *(__half2*)base = v0;
                *(__half2*)(base + 8 * DKdim) = v1;
            } else {
                float2 v0 = make_float2(c[i][j][0] + bb.x, c[i][j][1] + bb.y);
                float2 v1 = make_float2(c[i][j][2] + bb.x, c[i][j][3] + bb.y);
                *(float2*)((float*)Cout + (size_t)r0 * 1024 + n) = v0;
                *(float2*)((float*)Cout + (size_t)(r0 + 8) * 1024 + n) = v1;
            }
        }
    }
}

// ---------------------------------------------------------------------------
// Flash attention, fp16 MMA (m16n8k16), fp32 softmax/accum.
// CTA = (b,h) x 256 q rows, 256 thr (8 warps x 32 q-rows), K/V 64-row tiles
// double-buffered via cp.async. V B-fragments via ldmatrix.x4.trans.
// Smem unit: word=fp16x2, pitch PW=36 words (conflict-free frags + ldmatrix).
// ---------------------------------------------------------------------------
#define QROWS 256
#define PW 36

__global__ void __launch_bounds__(256, 1)
attn_f16(const __half* __restrict__ Q, const __half* __restrict__ Kg,
         const __half* __restrict__ Vg, __half* __restrict__ ctx)
{
    extern __shared__ uint32_t smw[];
    uint32_t* Qs = smw;                       // [256][PW]
    uint32_t* Ks = Qs + QROWS*PW;             // [2][64][PW]
    uint32_t* Vs = Ks + 2*64*PW;              // [2][64][PW]
    uint32_t* Ps = Vs + 2*64*PW;              // [256][PW]

    const int tid  = threadIdx.x;
    const int lane = tid & 31, warp = tid >> 5;
    const int bh = blockIdx.y;
    const int b  = bh >> 4, h = bh & 15;
    const int q0 = blockIdx.x * QROWS;

    const __half* Qp = Q  + ((size_t)bh * Sdim + q0) * DKdim;
    const __half* Kp = Kg + (size_t)bh * Sdim * DKdim;
    const __half* Vp = Vg + (size_t)bh * Sdim * DKdim;

    const uint32_t ksb = (uint32_t)__cvta_generic_to_shared(Ks);
    const uint32_t vsb = (uint32_t)__cvta_generic_to_shared(Vs);

#define ATTN_PRE(kt2, bs) do {                                              \
        const __half* Kt_ = Kp + (size_t)(kt2) * 64 * DKdim;                \
        const __half* Vt_ = Vp + (size_t)(kt2) * 64 * DKdim;                \
        const uint32_t kb_ = ksb + (bs) * (64*PW*4);                        \
        const uint32_t vb_ = vsb + (bs) * (64*PW*4);                        \
        _Pragma("unroll")                                                   \
        for (int p_ = 0; p_ < 2; p_++) {                                    \
            const int idx_ = tid + 256 * p_;                                \
            const int row_ = idx_ >> 3, c_ = idx_ & 7;                      \
            cp16(kb_ + (row_*PW + c_*4)*4, Kt_ + row_*DKdim + c_*8);        \
            cp16(vb_ + (row_*PW + c_*4)*4, Vt_ + row_*DKdim + c_*8);        \
        }                                                                   \
        asm volatile("cp.async.commit_group;");                             \
    } while (0)

    ATTN_PRE(0, 0);

    // Q tile: fp16 load, scale by 0.125 (exact pow2 in fp16)
    {
        const __half2 sc = __float2half2_rn(0.125f);
#pragma unroll
        for (int p = 0; p < 8; p++) {
            const int idx = tid + 256 * p;
            const int row = idx >> 3, c = idx & 7;
            uint4 v = *(const uint4*)(Qp + (size_t)row * DKdim + c * 8);
            __half2* hv = (__half2*)&v;
            hv[0] = __hmul2(hv[0], sc); hv[1] = __hmul2(hv[1], sc);
            hv[2] = __hmul2(hv[2], sc); hv[3] = __hmul2(hv[3], sc);
            *(uint4*)&Qs[row * PW + c * 4] = v;
        }
    }

    float o[2][8][4];
#pragma unroll
    for (int i = 0; i < 2; i++)
#pragma unroll
        for (int j = 0; j < 8; j++)
#pragma unroll
            for (int t = 0; t < 4; t++) o[i][j][t] = 0.f;
    float mrow[2][2] = {{-1e30f, -1e30f}, {-1e30f, -1e30f}};
    float lsum[2][2] = {{0.f, 0.f}, {0.f, 0.f}};

    const int rA = warp*32 + (lane >> 2);
    const int cL = lane & 3;
    const int nL = lane >> 2;

    for (int kt = 0; kt < Sdim/64; kt++) {
        const int buf = kt & 1;
        if (kt + 1 < Sdim/64) {
            ATTN_PRE(kt + 1, buf ^ 1);
            asm volatile("cp.async.wait_group 1;");
        } else {
            asm volatile("cp.async.wait_group 0;");
        }
        __syncthreads();

        const uint32_t* Kb = Ks + buf * (64*PW);
        const uint32_t  vbb = vsb + buf * (64*PW*4);

        // ---- S = Q K^T : 32 rows x 64 cols per warp, k = dk (4 k16 steps) ----
        float s[2][8][4];
#pragma unroll
        for (int i = 0; i < 2; i++)
#pragma unroll
            for (int j = 0; j < 8; j++)
#pragma unroll
                for (int t = 0; t < 4; t++) s[i][j][t] = 0.f;

#pragma unroll
        for (int ks = 0; ks < 4; ks++) {
            uint32_t a[2][4];
#pragma unroll
            for (int i = 0; i < 2; i++) {
                const uint32_t* qp = Qs + (rA + i*16) * PW + ks*8 + cL;
                a[i][0] = qp[0];
                a[i][1] = qp[8*PW];
                a[i][2] = qp[4];
                a[i][3] = qp[8*PW + 4];
            }
#pragma unroll
            for (int j = 0; j < 8; j++) {
                const uint32_t* kp = Kb + (j*8 + nL) * PW + ks*8 + cL;
                mma_f16(s[0][j], a[0], kp[0], kp[4]);
                mma_f16(s[1][j], a[1], kp[0], kp[4]);
            }
        }

        // ---- online softmax (fp32, unchanged) ----
#pragma unroll
        for (int i = 0; i < 2; i++) {
#pragma unroll
            for (int hh = 0; hh < 2; hh++) {
                float tm = -1e30f;
#pragma unroll
                for (int j = 0; j < 8; j++)
                    tm = fmaxf(tm, fmaxf(s[i][j][hh*2], s[i][j][hh*2+1]));
                tm = fmaxf(tm, __shfl_xor_sync(0xffffffffu, tm, 1));
                tm = fmaxf(tm, __shfl_xor_sync(0xffffffffu, tm, 2));
                const float mnew  = fmaxf(mrow[i][hh], tm);
                const float alpha = __expf(mrow[i][hh] - mnew);
                mrow[i][hh] = mnew;
                float rs = 0.f;
#pragma unroll
                for (int j = 0; j < 8; j++) {
                    const float p0 = __expf(s[i][j][hh*2]   - mnew);
                    const float p1 = __expf(s[i][j][hh*2+1] - mnew);
                    s[i][j][hh*2] = p0; s[i][j][hh*2+1] = p1;
                    rs += p0 + p1;
                }
                rs += __shfl_xor_sync(0xffffffffu, rs, 1);
                rs += __shfl_xor_sync(0xffffffffu, rs, 2);
                lsum[i][hh] = lsum[i][hh] * alpha + rs;
#pragma unroll
                for (int j = 0; j < 8; j++) {
                    o[i][j][hh*2]   *= alpha;
                    o[i][j][hh*2+1] *= alpha;
                }
            }
        }

        // ---- P -> smem as fp16x2 (warp-local rows) ----
#pragma unroll
        for (int i = 0; i < 2; i++) {
#pragma unroll
            for (int j = 0; j < 8; j++) {
#pragma unroll
                for (int hh = 0; hh < 2; hh++) {
                    Ps[(rA + i*16 + hh*8) * PW + j*4 + cL] =
                        h2u(__floats2half2_rn(s[i][j][hh*2], s[i][j][hh*2+1]));
                }
            }
        }
        __syncwarp();

        // ---- O += P V : A = P (k=kpos), B = V via ldmatrix.x4.trans ----
#pragma unroll
        for (int ks2 = 0; ks2 < 4; ks2++) {
            uint32_t a[2][4];
#pragma unroll
            for (int i = 0; i < 2; i++) {
                const uint32_t* pp = Ps + (rA + i*16) * PW + ks2*8 + cL;
                a[i][0] = pp[0];
                a[i][1] = pp[8*PW];
                a[i][2] = pp[4];
                a[i][3] = pp[8*PW + 4];
            }
            const uint32_t vrow = ks2*16 + (lane & 15);
#pragma unroll
            for (int jj = 0; jj < 4; jj++) {
                uint32_t r0, r1, r2, r3;
                const uint32_t addr = vbb + vrow * (PW*4) + jj*32 + ((lane >> 4) & 1) * 16;
                ldsm_x4_t(r0, r1, r2, r3, addr);
                mma_f16(o[0][2*jj],   a[0], r0, r1);
                mma_f16(o[1][2*jj],   a[1], r0, r1);
                mma_f16(o[0][2*jj+1], a[0], r2, r3);
                mma_f16(o[1][2*jj+1], a[1], r2, r3);
            }
        }

        __syncthreads();   // all warps done with buf before prefetch reuses it
    }

    // ---- epilogue: normalize, write ctx fp16 [b,s,d] ----
#pragma unroll
    for (int i = 0; i < 2; i++) {
#pragma unroll
        for (int hh = 0; hh < 2; hh++) {
            const float inv = 1.f / lsum[i][hh];
            const int srow = q0 + rA + i*16 + hh*8;
            __half* base = ctx + ((size_t)b * Sdim + srow) * Ddim + h * DKdim;
#pragma unroll
            for (int j = 0; j < 8; j++) {
                *(__half2*)(base + j*8 + 2*cL) =
                    __floats2half2_rn(o[i][j][hh*2] * inv, o[i][j][hh*2+1] * inv);
            }
        }
    }
}

// ---------------------------------------------------------------------------
extern "C" void kernel_launch(void* const* d_in, const int* in_sizes, int n_in,
                              void* d_out, int out_size)
{
    (void)in_sizes; (void)n_in; (void)out_size;
    const float* x  = (const float*)d_in[0];
    // d_in[1] = attention_mask (unused by reference forward)
    const float* Wq = (const float*)d_in[2];
    const float* bq = (const float*)d_in[3];
    const float* Wk = (const float*)d_in[4];
    const float* bk = (const float*)d_in[5];
    const float* Wv = (const float*)d_in[6];
    const float* bv = (const float*)d_in[7];
    const float* Wo = (const float*)d_in[8];
    const float* bo = (const float*)d_in[9];
    float* out = (float*)d_out;

    __half *Qh, *Kh, *Vh, *Ch, *Xh, *Wh;
    cudaGetSymbolAddress((void**)&Qh, g_Q);
    cudaGetSymbolAddress((void**)&Kh, g_K);
    cudaGetSymbolAddress((void**)&Vh, g_V);
    cudaGetSymbolAddress((void**)&Ch, g_ctx);
    cudaGetSymbolAddress((void**)&Xh, g_xh);
    cudaGetSymbolAddress((void**)&Wh, g_wh);

    const int GEMM_SMEM = 4 * GBUF * (int)sizeof(uint32_t);                 // 40960
    const int ATTN_SMEM = (QROWS*PW + 2*64*PW + 2*64*PW + QROWS*PW) * 4;    // 110592

    cudaFuncSetAttribute(gemm_f16<true>,
                         cudaFuncAttributeMaxDynamicSharedMemorySize, GEMM_SMEM);
    cudaFuncSetAttribute(gemm_f16<false>,
                         cudaFuncAttributeMaxDynamicSharedMemorySize, GEMM_SMEM);
    cudaFuncSetAttribute(attn_f16,
                         cudaFuncAttributeMaxDynamicSharedMemorySize, ATTN_SMEM);

    // fp16 conversion passes (round once at the producer)
    to_half_kernel<<<(Mtot*Ddim/8 + 255)/256, 256>>>(x, Xh, Mtot*Ddim/8);
    to_half_kernel<<<(Ddim*Ddim/8 + 255)/256, 256>>>(Wq, Wh + 0*Ddim*Ddim, Ddim*Ddim/8);
    to_half_kernel<<<(Ddim*Ddim/8 + 255)/256, 256>>>(Wk, Wh + 1*Ddim*Ddim, Ddim*Ddim/8);
    to_half_kernel<<<(Ddim*Ddim/8 + 255)/256, 256>>>(Wv, Wh + 2*Ddim*Ddim, Ddim*Ddim/8);
    to_half_kernel<<<(Ddim*Ddim/8 + 255)/256, 256>>>(Wo, Wh + 3*Ddim*Ddim, Ddim*Ddim/8);

    const dim3 gg(Ddim / 128, Mtot / 128);   // (8, 64)
    gemm_f16<true><<<gg, 256, GEMM_SMEM>>>(Xh, Wh + 0*Ddim*Ddim, bq, Qh);
    gemm_f16<true><<<gg, 256, GEMM_SMEM>>>(Xh, Wh + 1*Ddim*Ddim, bk, Kh);
    gemm_f16<true><<<gg, 256, GEMM_SMEM>>>(Xh, Wh + 2*Ddim*Ddim, bv, Vh);

    attn_f16<<<dim3(Sdim / QROWS, Bdim * Hdim), 256, ATTN_SMEM>>>(Qh, Kh, Vh, Ch);

    gemm_f16<false><<<gg, 256, GEMM_SMEM>>>(Ch, Wh + 3*Ddim*Ddim, bo, out);
}

// round 10
// speedup vs baseline: 6.3856x; 1.0801x over previous
#include <cuda_runtime.h>
#include <cuda_fp16.h>
#include <math.h>
#include <stdint.h>

#define Bdim 4
#define Sdim 2048
#define Ddim 1024
#define Hdim 16
#define DKdim 64
#define Mtot (Bdim*Sdim)   // 8192

// Scratch (device globals: sanctioned no-alloc workaround)
__device__ __half g_Q[Bdim*Hdim*Sdim*DKdim];   // [b,h,s,dk] fp16
__device__ __half g_K[Bdim*Hdim*Sdim*DKdim];
__device__ __half g_V[Bdim*Hdim*Sdim*DKdim];
__device__ __half g_ctx[Bdim*Sdim*Ddim];       // [b,s,d] fp16
__device__ __half g_xh[Mtot*Ddim];             // fp16 encoder input
__device__ __half g_wh[4*Ddim*Ddim];           // fp16 Wq,Wk,Wv,Wo

// ---------------------------------------------------------------------------
__device__ __forceinline__ void mma_f16(float c[4], const uint32_t a[4],
                                        uint32_t b0, uint32_t b1) {
    asm volatile(
        "mma.sync.aligned.m16n8k16.row.col.f32.f16.f16.f32 "
        "{%0,%1,%2,%3},{%4,%5,%6,%7},{%8,%9},{%0,%1,%2,%3};"
        : "+f"(c[0]), "+f"(c[1]), "+f"(c[2]), "+f"(c[3])
        : "r"(a[0]), "r"(a[1]), "r"(a[2]), "r"(a[3]), "r"(b0), "r"(b1));
}

__device__ __forceinline__ void ldsm_x4(uint32_t& r0, uint32_t& r1,
                                        uint32_t& r2, uint32_t& r3, uint32_t a) {
    asm volatile("ldmatrix.sync.aligned.m8n8.x4.shared.b16 {%0,%1,%2,%3}, [%4];"
                 : "=r"(r0), "=r"(r1), "=r"(r2), "=r"(r3) : "r"(a));
}

__device__ __forceinline__ void ldsm_x4_t(uint32_t& r0, uint32_t& r1,
                                          uint32_t& r2, uint32_t& r3, uint32_t a) {
    asm volatile("ldmatrix.sync.aligned.m8n8.x4.trans.shared.b16 {%0,%1,%2,%3}, [%4];"
                 : "=r"(r0), "=r"(r1), "=r"(r2), "=r"(r3) : "r"(a));
}

__device__ __forceinline__ void cp16(uint32_t dst, const void* src) {
    asm volatile("cp.async.cg.shared.global [%0], [%1], 16;" :: "r"(dst), "l"(src));
}

__device__ __forceinline__ uint32_t h2u(__half2 h) { return *(uint32_t*)&h; }

// ---------------------------------------------------------------------------
// fp32 -> fp16 conversion pass (8 elements / thread)
// ---------------------------------------------------------------------------
__global__ void to_half_kernel(const float* __restrict__ in,
                               __half* __restrict__ out, int n8)
{
    int i = blockIdx.x * 256 + threadIdx.x;
    if (i < n8) {
        const float4 a = ((const float4*)in)[2*i];
        const float4 b = ((const float4*)in)[2*i+1];
        uint4 o;
        o.x = h2u(__floats2half2_rn(a.x, a.y));
        o.y = h2u(__floats2half2_rn(a.z, a.w));
        o.z = h2u(__floats2half2_rn(b.x, b.y));
        o.w = h2u(__floats2half2_rn(b.z, b.w));
        ((uint4*)out)[i] = o;
    }
}

// ---------------------------------------------------------------------------
// fp16 tensor-core GEMM-NT body: C[m,n] = sum_k A[m,k]*W[n,k] + bias[n]
// BM=BN=128, BK=32 halfs, 256 thr, warp = 64x32, m16n8k16, ldmatrix frags.
// ---------------------------------------------------------------------------
#define PWG 20
#define GBUF (128*PWG)    // words per operand buffer

template<bool SCATTER>
__device__ __forceinline__ void gemm_body(const __half* __restrict__ A,
                                          const __half* __restrict__ W,
                                          const float* __restrict__ bias,
                                          void* __restrict__ Cout)
{
    extern __shared__ uint32_t smw[];
    uint32_t* Asw = smw;               // [2][128][PWG]
    uint32_t* Bsw = smw + 2*GBUF;      // [2][128][PWG]

    const int tid  = threadIdx.x;
    const int lane = tid & 31, warp = tid >> 5;
    const int wm   = warp >> 2, wn = warp & 3;
    const int m0   = blockIdx.y * 128, n0 = blockIdx.x * 128;
    const int cL   = lane & 3, nL = lane >> 2;

    // ldmatrix lane geometry
    const int lr8 = lane & 7, g = lane >> 3;
    const int arow = (g & 1) * 8, acol = (g >> 1) * 4;   // A-frag matrix order
    const int brow = (g >> 1) * 8, bcol = (g & 1) * 4;   // B-frag (2 n-groups packed)

    float c[4][4][4];
#pragma unroll
    for (int i = 0; i < 4; i++)
#pragma unroll
        for (int j = 0; j < 4; j++)
#pragma unroll
            for (int t = 0; t < 4; t++) c[i][j][t] = 0.f;

    const uint32_t asb = (uint32_t)__cvta_generic_to_shared(Asw);
    const uint32_t bsb = (uint32_t)__cvta_generic_to_shared(Bsw);

#define GEMM_PRE(kt, bs) do {                                               \
        const __half* Ag_ = A + (size_t)m0 * 1024 + (kt) * 32;              \
        const __half* Wg_ = W + (size_t)n0 * 1024 + (kt) * 32;              \
        const uint32_t as_ = asb + (bs) * (GBUF*4);                         \
        const uint32_t bs_ = bsb + (bs) * (GBUF*4);                         \
        _Pragma("unroll")                                                   \
        for (int p_ = 0; p_ < 2; p_++) {                                    \
            const int idx_ = tid + 256 * p_;                                \
            const int row_ = idx_ >> 2, c_ = idx_ & 3;                      \
            cp16(as_ + (row_*PWG + c_*4)*4, Ag_ + (size_t)row_*1024 + c_*8);\
            cp16(bs_ + (row_*PWG + c_*4)*4, Wg_ + (size_t)row_*1024 + c_*8);\
        }                                                                   \
        asm volatile("cp.async.commit_group;");                             \
    } while (0)

    GEMM_PRE(0, 0);

    for (int kt = 0; kt < 32; kt++) {
        if (kt + 1 < 32) {
            GEMM_PRE(kt + 1, (kt + 1) & 1);
            asm volatile("cp.async.wait_group 1;");
        } else {
            asm volatile("cp.async.wait_group 0;");
        }
        __syncthreads();

        const uint32_t Au = asb + ((kt & 1) * GBUF + (wm*64 + arow + lr8) * PWG + acol) * 4;
        const uint32_t Bu = bsb + ((kt & 1) * GBUF + (wn*32 + brow + lr8) * PWG + bcol) * 4;

#pragma unroll
        for (int ks = 0; ks < 2; ks++) {
            uint32_t a[4][4], b[4][2];
#pragma unroll
            for (int i = 0; i < 4; i++)
                ldsm_x4(a[i][0], a[i][1], a[i][2], a[i][3],
                        Au + (i*16*PWG + ks*8) * 4);
#pragma unroll
            for (int jp = 0; jp < 2; jp++)
                ldsm_x4(b[2*jp][0], b[2*jp][1], b[2*jp+1][0], b[2*jp+1][1],
                        Bu + (jp*16*PWG + ks*8) * 4);
#pragma unroll
            for (int i = 0; i < 4; i++)
#pragma unroll
                for (int j = 0; j < 4; j++)
                    mma_f16(c[i][j], a[i], b[j][0], b[j][1]);
        }
        __syncthreads();
    }

    // epilogue
#pragma unroll
    for (int i = 0; i < 4; i++) {
        const int r0 = m0 + wm*64 + i*16 + nL;
#pragma unroll
        for (int j = 0; j < 4; j++) {
            const int n = n0 + wn*32 + j*8 + 2*cL;
            const float2 bb = *(const float2*)(bias + n);
            if (SCATTER) {
                __half2 v0 = __floats2half2_rn(c[i][j][0] + bb.x, c[i][j][1] + bb.y);
                __half2 v1 = __floats2half2_rn(c[i][j][2] + bb.x, c[i][j][3] + bb.y);
                const int h_  = n >> 6, dk_ = n & 63;
                const int b_  = r0 >> 11, s_ = r0 & 2047;
                __half* base = (__half*)Cout + (((size_t)(b_*Hdim + h_) * Sdim + s_) * DKdim + dk_);
                *(__half2*)base = v0;
                *(__half2*)(base + 8 * DKdim) = v1;
            } else {
                float2 v0 = make_float2(c[i][j][0] + bb.x, c[i][j][1] + bb.y);
                float2 v1 = make_float2(c[i][j][2] + bb.x, c[i][j][3] + bb.y);
                *(float2*)((float*)Cout + (size_t)r0 * 1024 + n) = v0;
                *(float2*)((float*)Cout + (size_t)(r0 + 8) * 1024 + n) = v1;
            }
        }
    }
}

// Merged QKV projection: grid.z selects {Q,K,V}
__global__ void __launch_bounds__(256, 2)
gemm_qkv_f16(const __half* __restrict__ X, const __half* __restrict__ Wbase,
             const float* __restrict__ bq, const float* __restrict__ bk,
             const float* __restrict__ bv,
             __half* __restrict__ Qo, __half* __restrict__ Ko, __half* __restrict__ Vo)
{
    const int z = blockIdx.z;
    const __half* W = Wbase + (size_t)z * Ddim * Ddim;
    const float* bias = (z == 0) ? bq : (z == 1) ? bk : bv;
    __half* out = (z == 0) ? Qo : (z == 1) ? Ko : Vo;
    gemm_body<true>(X, W, bias, out);
}

__global__ void __launch_bounds__(256, 2)
gemm_o_f16(const __half* __restrict__ A, const __half* __restrict__ W,
           const float* __restrict__ bias, float* __restrict__ out)
{
    gemm_body<false>(A, W, bias, out);
}

// ---------------------------------------------------------------------------
// Flash attention, fp16 MMA, ldmatrix fragment loads everywhere.
// CTA = (b,h) x 256 q rows, 256 thr (8 warps x 32 q-rows), K/V 64-row tiles
// double-buffered via cp.async.
// ---------------------------------------------------------------------------
#define QROWS 256
#define PW 36

__global__ void __launch_bounds__(256, 1)
attn_f16(const __half* __restrict__ Q, const __half* __restrict__ Kg,
         const __half* __restrict__ Vg, __half* __restrict__ ctx)
{
    extern __shared__ uint32_t smw[];
    uint32_t* Qs = smw;                       // [256][PW]
    uint32_t* Ks = Qs + QROWS*PW;             // [2][64][PW]
    uint32_t* Vs = Ks + 2*64*PW;              // [2][64][PW]
    uint32_t* Ps = Vs + 2*64*PW;              // [256][PW]

    const int tid  = threadIdx.x;
    const int lane = tid & 31, warp = tid >> 5;
    const int bh = blockIdx.y;
    const int b  = bh >> 4, h = bh & 15;
    const int q0 = blockIdx.x * QROWS;

    const __half* Qp = Q  + ((size_t)bh * Sdim + q0) * DKdim;
    const __half* Kp = Kg + (size_t)bh * Sdim * DKdim;
    const __half* Vp = Vg + (size_t)bh * Sdim * DKdim;

    const uint32_t qsb = (uint32_t)__cvta_generic_to_shared(Qs);
    const uint32_t ksb = (uint32_t)__cvta_generic_to_shared(Ks);
    const uint32_t vsb = (uint32_t)__cvta_generic_to_shared(Vs);
    const uint32_t psb = (uint32_t)__cvta_generic_to_shared(Ps);

#define ATTN_PRE(kt2, bs) do {                                              \
        const __half* Kt_ = Kp + (size_t)(kt2) * 64 * DKdim;                \
        const __half* Vt_ = Vp + (size_t)(kt2) * 64 * DKdim;                \
        const uint32_t kb_ = ksb + (bs) * (64*PW*4);                        \
        const uint32_t vb_ = vsb + (bs) * (64*PW*4);                        \
        _Pragma("unroll")                                                   \
        for (int p_ = 0; p_ < 2; p_++) {                                    \
            const int idx_ = tid + 256 * p_;                                \
            const int row_ = idx_ >> 3, c_ = idx_ & 7;                      \
            cp16(kb_ + (row_*PW + c_*4)*4, Kt_ + row_*DKdim + c_*8);        \
            cp16(vb_ + (row_*PW + c_*4)*4, Vt_ + row_*DKdim + c_*8);        \
        }                                                                   \
        asm volatile("cp.async.commit_group;");                             \
    } while (0)

    ATTN_PRE(0, 0);

    // Q tile: fp16 load, scale by 0.125 (exact pow2 in fp16)
    {
        const __half2 sc = __float2half2_rn(0.125f);
#pragma unroll
        for (int p = 0; p < 8; p++) {
            const int idx = tid + 256 * p;
            const int row = idx >> 3, c = idx & 7;
            uint4 v = *(const uint4*)(Qp + (size_t)row * DKdim + c * 8);
            __half2* hv = (__half2*)&v;
            hv[0] = __hmul2(hv[0], sc); hv[1] = __hmul2(hv[1], sc);
            hv[2] = __hmul2(hv[2], sc); hv[3] = __hmul2(hv[3], sc);
            *(uint4*)&Qs[row * PW + c * 4] = v;
        }
    }

    float o[2][8][4];
#pragma unroll
    for (int i = 0; i < 2; i++)
#pragma unroll
        for (int j = 0; j < 8; j++)
#pragma unroll
            for (int t = 0; t < 4; t++) o[i][j][t] = 0.f;
    float mrow[2][2] = {{-1e30f, -1e30f}, {-1e30f, -1e30f}};
    float lsum[2][2] = {{0.f, 0.f}, {0.f, 0.f}};

    const int rA = warp*32 + (lane >> 2);
    const int cL = lane & 3;

    // ldmatrix lane geometry
    const int lr8 = lane & 7, g = lane >> 3;
    const int arow = (g & 1) * 8, acol = (g >> 1) * 4;
    const int brow = (g >> 1) * 8, bcol = (g & 1) * 4;

    const uint32_t Qu = qsb + ((warp*32 + arow + lr8) * PW + acol) * 4;
    const uint32_t Pu = psb + ((warp*32 + arow + lr8) * PW + acol) * 4;

    for (int kt = 0; kt < Sdim/64; kt++) {
        const int buf = kt & 1;
        if (kt + 1 < Sdim/64) {
            ATTN_PRE(kt + 1, buf ^ 1);
            asm volatile("cp.async.wait_group 1;");
        } else {
            asm volatile("cp.async.wait_group 0;");
        }
        __syncthreads();

        const uint32_t Ku = ksb + buf * (64*PW*4) + ((brow + lr8) * PW + bcol) * 4;
        const uint32_t vbb = vsb + buf * (64*PW*4);

        // ---- S = Q K^T : 32 rows x 64 cols per warp (4 k16 steps) ----
        float s[2][8][4];
#pragma unroll
        for (int i = 0; i < 2; i++)
#pragma unroll
            for (int j = 0; j < 8; j++)
#pragma unroll
                for (int t = 0; t < 4; t++) s[i][j][t] = 0.f;

#pragma unroll
        for (int ks = 0; ks < 4; ks++) {
            uint32_t a[2][4];
#pragma unroll
            for (int i = 0; i < 2; i++)
                ldsm_x4(a[i][0], a[i][1], a[i][2], a[i][3],
                        Qu + (i*16*PW + ks*8) * 4);
#pragma unroll
            for (int jp = 0; jp < 4; jp++) {
                uint32_t b0, b1, b2, b3;
                ldsm_x4(b0, b1, b2, b3, Ku + (jp*16*PW + ks*8) * 4);
                mma_f16(s[0][2*jp],   a[0], b0, b1);
                mma_f16(s[1][2*jp],   a[1], b0, b1);
                mma_f16(s[0][2*jp+1], a[0], b2, b3);
                mma_f16(s[1][2*jp+1], a[1], b2, b3);
            }
        }

        // ---- online softmax (fp32, unchanged) ----
#pragma unroll
        for (int i = 0; i < 2; i++) {
#pragma unroll
            for (int hh = 0; hh < 2; hh++) {
                float tm = -1e30f;
#pragma unroll
                for (int j = 0; j < 8; j++)
                    tm = fmaxf(tm, fmaxf(s[i][j][hh*2], s[i][j][hh*2+1]));
                tm = fmaxf(tm, __shfl_xor_sync(0xffffffffu, tm, 1));
                tm = fmaxf(tm, __shfl_xor_sync(0xffffffffu, tm, 2));
                const float mnew  = fmaxf(mrow[i][hh], tm);
                const float alpha = __expf(mrow[i][hh] - mnew);
                mrow[i][hh] = mnew;
                float rs = 0.f;
#pragma unroll
                for (int j = 0; j < 8; j++) {
                    const float p0 = __expf(s[i][j][hh*2]   - mnew);
                    const float p1 = __expf(s[i][j][hh*2+1] - mnew);
                    s[i][j][hh*2] = p0; s[i][j][hh*2+1] = p1;
                    rs += p0 + p1;
                }
                rs += __shfl_xor_sync(0xffffffffu, rs, 1);
                rs += __shfl_xor_sync(0xffffffffu, rs, 2);
                lsum[i][hh] = lsum[i][hh] * alpha + rs;
#pragma unroll
                for (int j = 0; j < 8; j++) {
                    o[i][j][hh*2]   *= alpha;
                    o[i][j][hh*2+1] *= alpha;
                }
            }
        }

        // ---- P -> smem as fp16x2 (warp-local rows) ----
#pragma unroll
        for (int i = 0; i < 2; i++) {
#pragma unroll
            for (int j = 0; j < 8; j++) {
#pragma unroll
                for (int hh = 0; hh < 2; hh++) {
                    Ps[(rA + i*16 + hh*8) * PW + j*4 + cL] =
                        h2u(__floats2half2_rn(s[i][j][hh*2], s[i][j][hh*2+1]));
                }
            }
        }
        __syncwarp();

        // ---- O += P V : A = P via ldmatrix, B = V via ldmatrix.trans ----
#pragma unroll
        for (int ks2 = 0; ks2 < 4; ks2++) {
            uint32_t a[2][4];
#pragma unroll
            for (int i = 0; i < 2; i++)
                ldsm_x4(a[i][0], a[i][1], a[i][2], a[i][3],
                        Pu + (i*16*PW + ks2*8) * 4);
            const uint32_t vrow = ks2*16 + (lane & 15);
#pragma unroll
            for (int jj = 0; jj < 4; jj++) {
                uint32_t r0, r1, r2, r3;
                const uint32_t addr = vbb + vrow * (PW*4) + jj*32 + ((lane >> 4) & 1) * 16;
                ldsm_x4_t(r0, r1, r2, r3, addr);
                mma_f16(o[0][2*jj],   a[0], r0, r1);
                mma_f16(o[1][2*jj],   a[1], r0, r1);
                mma_f16(o[0][2*jj+1], a[0], r2, r3);
                mma_f16(o[1][2*jj+1], a[1], r2, r3);
            }
        }

        __syncthreads();   // all warps done with buf before prefetch reuses it
    }

    // ---- epilogue: normalize, write ctx fp16 [b,s,d] ----
#pragma unroll
    for (int i = 0; i < 2; i++) {
#pragma unroll
        for (int hh = 0; hh < 2; hh++) {
            const float inv = 1.f / lsum[i][hh];
            const int srow = q0 + rA + i*16 + hh*8;
            __half* base = ctx + ((size_t)b * Sdim + srow) * Ddim + h * DKdim;
#pragma unroll
            for (int j = 0; j < 8; j++) {
                *(__half2*)(base + j*8 + 2*cL) =
                    __floats2half2_rn(o[i][j][hh*2] * inv, o[i][j][hh*2+1] * inv);
            }
        }
    }
}

// ---------------------------------------------------------------------------
extern "C" void kernel_launch(void* const* d_in, const int* in_sizes, int n_in,
                              void* d_out, int out_size)
{
    (void)in_sizes; (void)n_in; (void)out_size;
    const float* x  = (const float*)d_in[0];
    // d_in[1] = attention_mask (unused by reference forward)
    const float* Wq = (const float*)d_in[2];
    const float* bq = (const float*)d_in[3];
    const float* Wk = (const float*)d_in[4];
    const float* bk = (const float*)d_in[5];
    const float* Wv = (const float*)d_in[6];
    const float* bv = (const float*)d_in[7];
    const float* Wo = (const float*)d_in[8];
    const float* bo = (const float*)d_in[9];
    float* out = (float*)d_out;

    __half *Qh, *Kh, *Vh, *Ch, *Xh, *Wh;
    cudaGetSymbolAddress((void**)&Qh, g_Q);
    cudaGetSymbolAddress((void**)&Kh, g_K);
    cudaGetSymbolAddress((void**)&Vh, g_V);
    cudaGetSymbolAddress((void**)&Ch, g_ctx);
    cudaGetSymbolAddress((void**)&Xh, g_xh);
    cudaGetSymbolAddress((void**)&Wh, g_wh);

    const int GEMM_SMEM = 4 * GBUF * (int)sizeof(uint32_t);                 // 40960
    const int ATTN_SMEM = (QROWS*PW + 2*64*PW + 2*64*PW + QROWS*PW) * 4;    // 110592

    cudaFuncSetAttribute(gemm_qkv_f16,
                         cudaFuncAttributeMaxDynamicSharedMemorySize, GEMM_SMEM);
    cudaFuncSetAttribute(gemm_o_f16,
                         cudaFuncAttributeMaxDynamicSharedMemorySize, GEMM_SMEM);
    cudaFuncSetAttribute(attn_f16,
                         cudaFuncAttributeMaxDynamicSharedMemorySize, ATTN_SMEM);

    // fp16 conversion passes (round once at the producer)
    to_half_kernel<<<(Mtot*Ddim/8 + 255)/256, 256>>>(x, Xh, Mtot*Ddim/8);
    to_half_kernel<<<(Ddim*Ddim/8 + 255)/256, 256>>>(Wq, Wh + 0*Ddim*Ddim, Ddim*Ddim/8);
    to_half_kernel<<<(Ddim*Ddim/8 + 255)/256, 256>>>(Wk, Wh + 1*Ddim*Ddim, Ddim*Ddim/8);
    to_half_kernel<<<(Ddim*Ddim/8 + 255)/256, 256>>>(Wv, Wh + 2*Ddim*Ddim, Ddim*Ddim/8);
    to_half_kernel<<<(Ddim*Ddim/8 + 255)/256, 256>>>(Wo, Wh + 3*Ddim*Ddim, Ddim*Ddim/8);

    // Merged QKV projection (grid.z = 3), then attention, then output proj
    gemm_qkv_f16<<<dim3(Ddim/128, Mtot/128, 3), 256, GEMM_SMEM>>>(
        Xh, Wh, bq, bk, bv, Qh, Kh, Vh);

    attn_f16<<<dim3(Sdim / QROWS, Bdim * Hdim), 256, ATTN_SMEM>>>(Qh, Kh, Vh, Ch);

    gemm_o_f16<<<dim3(Ddim/128, Mtot/128), 256, GEMM_SMEM>>>(
        Ch, Wh + 3*Ddim*Ddim, bo, out);
}

// round 11
// speedup vs baseline: 6.8380x; 1.0708x over previous
#include <cuda_runtime.h>
#include <cuda_fp16.h>
#include <math.h>
#include <stdint.h>

#define Bdim 4
#define Sdim 2048
#define Ddim 1024
#define Hdim 16
#define DKdim 64
#define Mtot (Bdim*Sdim)   // 8192

// Scratch (device globals: sanctioned no-alloc workaround)
__device__ __half g_Q[Bdim*Hdim*Sdim*DKdim];   // [b,h,s,dk] fp16
__device__ __half g_K[Bdim*Hdim*Sdim*DKdim];
__device__ __half g_V[Bdim*Hdim*Sdim*DKdim];
__device__ __half g_ctx[Bdim*Sdim*Ddim];       // [b,s,d] fp16
__device__ __half g_xh[Mtot*Ddim];             // fp16 encoder input
__device__ __half g_wh[4*Ddim*Ddim];           // fp16 Wq,Wk,Wv,Wo

// ---------------------------------------------------------------------------
__device__ __forceinline__ void mma_f16(float c[4], const uint32_t a[4],
                                        uint32_t b0, uint32_t b1) {
    asm volatile(
        "mma.sync.aligned.m16n8k16.row.col.f32.f16.f16.f32 "
        "{%0,%1,%2,%3},{%4,%5,%6,%7},{%8,%9},{%0,%1,%2,%3};"
        : "+f"(c[0]), "+f"(c[1]), "+f"(c[2]), "+f"(c[3])
        : "r"(a[0]), "r"(a[1]), "r"(a[2]), "r"(a[3]), "r"(b0), "r"(b1));
}

__device__ __forceinline__ void ldsm_x4(uint32_t& r0, uint32_t& r1,
                                        uint32_t& r2, uint32_t& r3, uint32_t a) {
    asm volatile("ldmatrix.sync.aligned.m8n8.x4.shared.b16 {%0,%1,%2,%3}, [%4];"
                 : "=r"(r0), "=r"(r1), "=r"(r2), "=r"(r3) : "r"(a));
}

__device__ __forceinline__ void ldsm_x4_t(uint32_t& r0, uint32_t& r1,
                                          uint32_t& r2, uint32_t& r3, uint32_t a) {
    asm volatile("ldmatrix.sync.aligned.m8n8.x4.trans.shared.b16 {%0,%1,%2,%3}, [%4];"
                 : "=r"(r0), "=r"(r1), "=r"(r2), "=r"(r3) : "r"(a));
}

__device__ __forceinline__ void cp16(uint32_t dst, const void* src) {
    asm volatile("cp.async.cg.shared.global [%0], [%1], 16;" :: "r"(dst), "l"(src));
}

__device__ __forceinline__ uint32_t h2u(__half2 h) { return *(uint32_t*)&h; }

// ---------------------------------------------------------------------------
// fp32 -> fp16 conversion passes (8 elements / thread)
// ---------------------------------------------------------------------------
__device__ __forceinline__ void conv8(const float* __restrict__ in,
                                      __half* __restrict__ out, int i) {
    const float4 a = ((const float4*)in)[2*i];
    const float4 b = ((const float4*)in)[2*i+1];
    uint4 o;
    o.x = h2u(__floats2half2_rn(a.x, a.y));
    o.y = h2u(__floats2half2_rn(a.z, a.w));
    o.z = h2u(__floats2half2_rn(b.x, b.y));
    o.w = h2u(__floats2half2_rn(b.z, b.w));
    ((uint4*)out)[i] = o;
}

__global__ void to_half_kernel(const float* __restrict__ in,
                               __half* __restrict__ out, int n8)
{
    int i = blockIdx.x * 256 + threadIdx.x;
    if (i < n8) conv8(in, out, i);
}

// All 4 weight matrices in one launch (grid.z selects the matrix)
__global__ void to_half_w4_kernel(const float* __restrict__ w0,
                                  const float* __restrict__ w1,
                                  const float* __restrict__ w2,
                                  const float* __restrict__ w3,
                                  __half* __restrict__ out)
{
    const int z = blockIdx.z;
    const float* in = (z == 0) ? w0 : (z == 1) ? w1 : (z == 2) ? w2 : w3;
    const int i = blockIdx.x * 256 + threadIdx.x;   // < Ddim*Ddim/8 by grid
    conv8(in, out + (size_t)z * Ddim * Ddim, i);
}

// ---------------------------------------------------------------------------
// fp16 tensor-core GEMM-NT body: C[m,n] = sum_k A[m,k]*W[n,k] + bias[n]
// BM=BN=128, BK=32 halfs, 256 thr, warp = 64x32, m16n8k16, ldmatrix frags.
// ---------------------------------------------------------------------------
#define PWG 20
#define GBUF (128*PWG)    // words per operand buffer

template<bool SCATTER>
__device__ __forceinline__ void gemm_body(const __half* __restrict__ A,
                                          const __half* __restrict__ W,
                                          const float* __restrict__ bias,
                                          void* __restrict__ Cout)
{
    extern __shared__ uint32_t smw[];
    uint32_t* Asw = smw;               // [2][128][PWG]
    uint32_t* Bsw = smw + 2*GBUF;      // [2][128][PWG]

    const int tid  = threadIdx.x;
    const int lane = tid & 31, warp = tid >> 5;
    const int wm   = warp >> 2, wn = warp & 3;
    const int m0   = blockIdx.y * 128, n0 = blockIdx.x * 128;
    const int cL   = lane & 3, nL = lane >> 2;

    // ldmatrix lane geometry
    const int lr8 = lane & 7, g = lane >> 3;
    const int arow = (g & 1) * 8, acol = (g >> 1) * 4;   // A-frag matrix order
    const int brow = (g >> 1) * 8, bcol = (g & 1) * 4;   // B-frag (2 n-groups packed)

    float c[4][4][4];
#pragma unroll
    for (int i = 0; i < 4; i++)
#pragma unroll
        for (int j = 0; j < 4; j++)
#pragma unroll
            for (int t = 0; t < 4; t++) c[i][j][t] = 0.f;

    const uint32_t asb = (uint32_t)__cvta_generic_to_shared(Asw);
    const uint32_t bsb = (uint32_t)__cvta_generic_to_shared(Bsw);

#define GEMM_PRE(kt, bs) do {                                               \
        const __half* Ag_ = A + (size_t)m0 * 1024 + (kt) * 32;              \
        const __half* Wg_ = W + (size_t)n0 * 1024 + (kt) * 32;              \
        const uint32_t as_ = asb + (bs) * (GBUF*4);                         \
        const uint32_t bs_ = bsb + (bs) * (GBUF*4);                         \
        _Pragma("unroll")                                                   \
        for (int p_ = 0; p_ < 2; p_++) {                                    \
            const int idx_ = tid + 256 * p_;                                \
            const int row_ = idx_ >> 2, c_ = idx_ & 3;                      \
            cp16(as_ + (row_*PWG + c_*4)*4, Ag_ + (size_t)row_*1024 + c_*8);\
            cp16(bs_ + (row_*PWG + c_*4)*4, Wg_ + (size_t)row_*1024 + c_*8);\
        }                                                                   \
        asm volatile("cp.async.commit_group;");                             \
    } while (0)

    GEMM_PRE(0, 0);

    for (int kt = 0; kt < 32; kt++) {
        if (kt + 1 < 32) {
            GEMM_PRE(kt + 1, (kt + 1) & 1);
            asm volatile("cp.async.wait_group 1;");
        } else {
            asm volatile("cp.async.wait_group 0;");
        }
        __syncthreads();

        const uint32_t Au = asb + ((kt & 1) * GBUF + (wm*64 + arow + lr8) * PWG + acol) * 4;
        const uint32_t Bu = bsb + ((kt & 1) * GBUF + (wn*32 + brow + lr8) * PWG + bcol) * 4;

#pragma unroll
        for (int ks = 0; ks < 2; ks++) {
            uint32_t a[4][4], b[4][2];
#pragma unroll
            for (int i = 0; i < 4; i++)
                ldsm_x4(a[i][0], a[i][1], a[i][2], a[i][3],
                        Au + (i*16*PWG + ks*8) * 4);
#pragma unroll
            for (int jp = 0; jp < 2; jp++)
                ldsm_x4(b[2*jp][0], b[2*jp][1], b[2*jp+1][0], b[2*jp+1][1],
                        Bu + (jp*16*PWG + ks*8) * 4);
#pragma unroll
            for (int i = 0; i < 4; i++)
#pragma unroll
                for (int j = 0; j < 4; j++)
                    mma_f16(c[i][j], a[i], b[j][0], b[j][1]);
        }
        __syncthreads();
    }

    // epilogue
#pragma unroll
    for (int i = 0; i < 4; i++) {
        const int r0 = m0 + wm*64 + i*16 + nL;
#pragma unroll
        for (int j = 0; j < 4; j++) {
            const int n = n0 + wn*32 + j*8 + 2*cL;
            const float2 bb = *(const float2*)(bias + n);
            if (SCATTER) {
                __half2 v0 = __floats2half2_rn(c[i][j][0] + bb.x, c[i][j][1] + bb.y);
                __half2 v1 = __floats2half2_rn(c[i][j][2] + bb.x, c[i][j][3] + bb.y);
                const int h_  = n >> 6, dk_ = n & 63;
                const int b_  = r0 >> 11, s_ = r0 & 2047;
                __half* base = (__half*)Cout + (((size_t)(b_*Hdim + h_) * Sdim + s_) * DKdim + dk_);
                *(__half2*)base = v0;
                *(__half2*)(base + 8 * DKdim) = v1;
            } else {
                float2 v0 = make_float2(c[i][j][0] + bb.x, c[i][j][1] + bb.y);
                float2 v1 = make_float2(c[i][j][2] + bb.x, c[i][j][3] + bb.y);
                *(float2*)((float*)Cout + (size_t)r0 * 1024 + n) = v0;
                *(float2*)((float*)Cout + (size_t)(r0 + 8) * 1024 + n) = v1;
            }
        }
    }
}

// Merged QKV projection: grid.z selects {Q,K,V}
__global__ void __launch_bounds__(256, 2)
gemm_qkv_f16(const __half* __restrict__ X, const __half* __restrict__ Wbase,
             const float* __restrict__ bq, const float* __restrict__ bk,
             const float* __restrict__ bv,
             __half* __restrict__ Qo, __half* __restrict__ Ko, __half* __restrict__ Vo)
{
    const int z = blockIdx.z;
    const __half* W = Wbase + (size_t)z * Ddim * Ddim;
    const float* bias = (z == 0) ? bq : (z == 1) ? bk : bv;
    __half* out = (z == 0) ? Qo : (z == 1) ? Ko : Vo;
    gemm_body<true>(X, W, bias, out);
}

__global__ void __launch_bounds__(256, 2)
gemm_o_f16(const __half* __restrict__ A, const __half* __restrict__ W,
           const float* __restrict__ bias, float* __restrict__ out)
{
    gemm_body<false>(A, W, bias, out);
}

// ---------------------------------------------------------------------------
// Flash attention, fp16 MMA, ldmatrix Q/K/V loads, P kept in REGISTERS
// (FA2 repack: S C-fragment layout == PV A-fragment layout).
// CTA = (b,h) x 256 q rows, 256 thr (8 warps x 32 q-rows), K/V 64-row tiles
// double-buffered via cp.async.
// ---------------------------------------------------------------------------
#define QROWS 256
#define PW 36

__global__ void __launch_bounds__(256, 1)
attn_f16(const __half* __restrict__ Q, const __half* __restrict__ Kg,
         const __half* __restrict__ Vg, __half* __restrict__ ctx)
{
    extern __shared__ uint32_t smw[];
    uint32_t* Qs = smw;                       // [256][PW]
    uint32_t* Ks = Qs + QROWS*PW;             // [2][64][PW]
    uint32_t* Vs = Ks + 2*64*PW;              // [2][64][PW]

    const int tid  = threadIdx.x;
    const int lane = tid & 31, warp = tid >> 5;
    const int bh = blockIdx.y;
    const int b  = bh >> 4, h = bh & 15;
    const int q0 = blockIdx.x * QROWS;

    const __half* Qp = Q  + ((size_t)bh * Sdim + q0) * DKdim;
    const __half* Kp = Kg + (size_t)bh * Sdim * DKdim;
    const __half* Vp = Vg + (size_t)bh * Sdim * DKdim;

    const uint32_t qsb = (uint32_t)__cvta_generic_to_shared(Qs);
    const uint32_t ksb = (uint32_t)__cvta_generic_to_shared(Ks);
    const uint32_t vsb = (uint32_t)__cvta_generic_to_shared(Vs);

#define ATTN_PRE(kt2, bs) do {                                              \
        const __half* Kt_ = Kp + (size_t)(kt2) * 64 * DKdim;                \
        const __half* Vt_ = Vp + (size_t)(kt2) * 64 * DKdim;                \
        const uint32_t kb_ = ksb + (bs) * (64*PW*4);                        \
        const uint32_t vb_ = vsb + (bs) * (64*PW*4);                        \
        _Pragma("unroll")                                                   \
        for (int p_ = 0; p_ < 2; p_++) {                                    \
            const int idx_ = tid + 256 * p_;                                \
            const int row_ = idx_ >> 3, c_ = idx_ & 7;                      \
            cp16(kb_ + (row_*PW + c_*4)*4, Kt_ + row_*DKdim + c_*8);        \
            cp16(vb_ + (row_*PW + c_*4)*4, Vt_ + row_*DKdim + c_*8);        \
        }                                                                   \
        asm volatile("cp.async.commit_group;");                             \
    } while (0)

    ATTN_PRE(0, 0);

    // Q tile: fp16 load, scale by 0.125 (exact pow2 in fp16)
    {
        const __half2 sc = __float2half2_rn(0.125f);
#pragma unroll
        for (int p = 0; p < 8; p++) {
            const int idx = tid + 256 * p;
            const int row = idx >> 3, c = idx & 7;
            uint4 v = *(const uint4*)(Qp + (size_t)row * DKdim + c * 8);
            __half2* hv = (__half2*)&v;
            hv[0] = __hmul2(hv[0], sc); hv[1] = __hmul2(hv[1], sc);
            hv[2] = __hmul2(hv[2], sc); hv[3] = __hmul2(hv[3], sc);
            *(uint4*)&Qs[row * PW + c * 4] = v;
        }
    }

    float o[2][8][4];
#pragma unroll
    for (int i = 0; i < 2; i++)
#pragma unroll
        for (int j = 0; j < 8; j++)
#pragma unroll
            for (int t = 0; t < 4; t++) o[i][j][t] = 0.f;
    float mrow[2][2] = {{-1e30f, -1e30f}, {-1e30f, -1e30f}};
    float lsum[2][2] = {{0.f, 0.f}, {0.f, 0.f}};

    const int cL = lane & 3;

    // ldmatrix lane geometry
    const int lr8 = lane & 7, g = lane >> 3;
    const int arow = (g & 1) * 8, acol = (g >> 1) * 4;
    const int brow = (g >> 1) * 8, bcol = (g & 1) * 4;

    const uint32_t Qu = qsb + ((warp*32 + arow + lr8) * PW + acol) * 4;

    for (int kt = 0; kt < Sdim/64; kt++) {
        const int buf = kt & 1;
        if (kt + 1 < Sdim/64) {
            ATTN_PRE(kt + 1, buf ^ 1);
            asm volatile("cp.async.wait_group 1;");
        } else {
            asm volatile("cp.async.wait_group 0;");
        }
        __syncthreads();

        const uint32_t Ku = ksb + buf * (64*PW*4) + ((brow + lr8) * PW + bcol) * 4;
        const uint32_t vbb = vsb + buf * (64*PW*4);

        // ---- S = Q K^T : 32 rows x 64 cols per warp (4 k16 steps) ----
        float s[2][8][4];
#pragma unroll
        for (int i = 0; i < 2; i++)
#pragma unroll
            for (int j = 0; j < 8; j++)
#pragma unroll
                for (int t = 0; t < 4; t++) s[i][j][t] = 0.f;

#pragma unroll
        for (int ks = 0; ks < 4; ks++) {
            uint32_t a[2][4];
#pragma unroll
            for (int i = 0; i < 2; i++)
                ldsm_x4(a[i][0], a[i][1], a[i][2], a[i][3],
                        Qu + (i*16*PW + ks*8) * 4);
#pragma unroll
            for (int jp = 0; jp < 4; jp++) {
                uint32_t b0, b1, b2, b3;
                ldsm_x4(b0, b1, b2, b3, Ku + (jp*16*PW + ks*8) * 4);
                mma_f16(s[0][2*jp],   a[0], b0, b1);
                mma_f16(s[1][2*jp],   a[1], b0, b1);
                mma_f16(s[0][2*jp+1], a[0], b2, b3);
                mma_f16(s[1][2*jp+1], a[1], b2, b3);
            }
        }

        // ---- online softmax (fp32, unchanged) ----
#pragma unroll
        for (int i = 0; i < 2; i++) {
#pragma unroll
            for (int hh = 0; hh < 2; hh++) {
                float tm = -1e30f;
#pragma unroll
                for (int j = 0; j < 8; j++)
                    tm = fmaxf(tm, fmaxf(s[i][j][hh*2], s[i][j][hh*2+1]));
                tm = fmaxf(tm, __shfl_xor_sync(0xffffffffu, tm, 1));
                tm = fmaxf(tm, __shfl_xor_sync(0xffffffffu, tm, 2));
                const float mnew  = fmaxf(mrow[i][hh], tm);
                const float alpha = __expf(mrow[i][hh] - mnew);
                mrow[i][hh] = mnew;
                float rs = 0.f;
#pragma unroll
                for (int j = 0; j < 8; j++) {
                    const float p0 = __expf(s[i][j][hh*2]   - mnew);
                    const float p1 = __expf(s[i][j][hh*2+1] - mnew);
                    s[i][j][hh*2] = p0; s[i][j][hh*2+1] = p1;
                    rs += p0 + p1;
                }
                rs += __shfl_xor_sync(0xffffffffu, rs, 1);
                rs += __shfl_xor_sync(0xffffffffu, rs, 2);
                lsum[i][hh] = lsum[i][hh] * alpha + rs;
#pragma unroll
                for (int j = 0; j < 8; j++) {
                    o[i][j][hh*2]   *= alpha;
                    o[i][j][hh*2+1] *= alpha;
                }
            }
        }

        // ---- O += P V : P repacked in registers (C-frag == A-frag layout),
        //      B = V via ldmatrix.trans. No smem round-trip, no extra sync.
#pragma unroll
        for (int ks2 = 0; ks2 < 4; ks2++) {
            uint32_t a[2][4];
#pragma unroll
            for (int i = 0; i < 2; i++) {
                a[i][0] = h2u(__floats2half2_rn(s[i][2*ks2][0],   s[i][2*ks2][1]));
                a[i][1] = h2u(__floats2half2_rn(s[i][2*ks2][2],   s[i][2*ks2][3]));
                a[i][2] = h2u(__floats2half2_rn(s[i][2*ks2+1][0], s[i][2*ks2+1][1]));
                a[i][3] = h2u(__floats2half2_rn(s[i][2*ks2+1][2], s[i][2*ks2+1][3]));
            }
            const uint32_t vrow = ks2*16 + (lane & 15);
#pragma unroll
            for (int jj = 0; jj < 4; jj++) {
                uint32_t r0, r1, r2, r3;
                const uint32_t addr = vbb + vrow * (PW*4) + jj*32 + ((lane >> 4) & 1) * 16;
                ldsm_x4_t(r0, r1, r2, r3, addr);
                mma_f16(o[0][2*jj],   a[0], r0, r1);
                mma_f16(o[1][2*jj],   a[1], r0, r1);
                mma_f16(o[0][2*jj+1], a[0], r2, r3);
                mma_f16(o[1][2*jj+1], a[1], r2, r3);
            }
        }

        __syncthreads();   // all warps done with buf before prefetch reuses it
    }

    // ---- epilogue: normalize, write ctx fp16 [b,s,d] ----
    const int rA = warp*32 + (lane >> 2);
#pragma unroll
    for (int i = 0; i < 2; i++) {
#pragma unroll
        for (int hh = 0; hh < 2; hh++) {
            const float inv = 1.f / lsum[i][hh];
            const int srow = q0 + rA + i*16 + hh*8;
            __half* base = ctx + ((size_t)b * Sdim + srow) * Ddim + h * DKdim;
#pragma unroll
            for (int j = 0; j < 8; j++) {
                *(__half2*)(base + j*8 + 2*cL) =
                    __floats2half2_rn(o[i][j][hh*2] * inv, o[i][j][hh*2+1] * inv);
            }
        }
    }
}

// ---------------------------------------------------------------------------
extern "C" void kernel_launch(void* const* d_in, const int* in_sizes, int n_in,
                              void* d_out, int out_size)
{
    (void)in_sizes; (void)n_in; (void)out_size;
    const float* x  = (const float*)d_in[0];
    // d_in[1] = attention_mask (unused by reference forward)
    const float* Wq = (const float*)d_in[2];
    const float* bq = (const float*)d_in[3];
    const float* Wk = (const float*)d_in[4];
    const float* bk = (const float*)d_in[5];
    const float* Wv = (const float*)d_in[6];
    const float* bv = (const float*)d_in[7];
    const float* Wo = (const float*)d_in[8];
    const float* bo = (const float*)d_in[9];
    float* out = (float*)d_out;

    __half *Qh, *Kh, *Vh, *Ch, *Xh, *Wh;
    cudaGetSymbolAddress((void**)&Qh, g_Q);
    cudaGetSymbolAddress((void**)&Kh, g_K);
    cudaGetSymbolAddress((void**)&Vh, g_V);
    cudaGetSymbolAddress((void**)&Ch, g_ctx);
    cudaGetSymbolAddress((void**)&Xh, g_xh);
    cudaGetSymbolAddress((void**)&Wh, g_wh);

    const int GEMM_SMEM = 4 * GBUF * (int)sizeof(uint32_t);          // 40960
    const int ATTN_SMEM = (QROWS*PW + 2*64*PW + 2*64*PW) * 4;        // 73728

    cudaFuncSetAttribute(gemm_qkv_f16,
                         cudaFuncAttributeMaxDynamicSharedMemorySize, GEMM_SMEM);
    cudaFuncSetAttribute(gemm_o_f16,
                         cudaFuncAttributeMaxDynamicSharedMemorySize, GEMM_SMEM);
    cudaFuncSetAttribute(attn_f16,
                         cudaFuncAttributeMaxDynamicSharedMemorySize, ATTN_SMEM);

    // fp16 conversion: input (1 launch) + all four weights (1 launch, grid.z=4)
    to_half_kernel<<<(Mtot*Ddim/8 + 255)/256, 256>>>(x, Xh, Mtot*Ddim/8);
    to_half_w4_kernel<<<dim3(Ddim*Ddim/8/256, 1, 4), 256>>>(Wq, Wk, Wv, Wo, Wh);

    // Merged QKV projection (grid.z = 3), then attention, then output proj
    gemm_qkv_f16<<<dim3(Ddim/128, Mtot/128, 3), 256, GEMM_SMEM>>>(
        Xh, Wh, bq, bk, bv, Qh, Kh, Vh);

    attn_f16<<<dim3(Sdim / QROWS, Bdim * Hdim), 256, ATTN_SMEM>>>(Qh, Kh, Vh, Ch);

    gemm_o_f16<<<dim3(Ddim/128, Mtot/128), 256, GEMM_SMEM>>>(
        Ch, Wh + 3*Ddim*Ddim, bo, out);
}